// round 1
// baseline (speedup 1.0000x reference)
#include <cuda_runtime.h>
#include <math.h>

#define ALPHA_SLOPE 0.2f
#define NEG_INF_F   -9000000000000000.0f

// Problem shape (fixed by setup_inputs)
#define BB    16
#define NN    1024
#define FIN   1024
#define FOUT  512
#define MTOT  (BB*NN)        // 16384

// ---------------- scratch (static device globals; no runtime alloc) ----------
__device__ float d_h  [MTOT * FOUT];        // 32 MB
__device__ float d_f1 [MTOT];
__device__ float d_f2 [MTOT];
__device__ float d_att[(size_t)MTOT * NN];  // 64 MB (unnormalized softmax numerators)
__device__ float d_inv[MTOT];               // 1/rowsum
__device__ float d_agg[MTOT * FOUT];        // 32 MB

// ---------------- GEMM 1: h = x @ W  (M=16384, K=1024, N=512) ----------------
// 64x64 tile, BK=16, 256 threads, 4x4 per thread.
__global__ void k_gemm_h(const float* __restrict__ X, const float* __restrict__ W)
{
    const int BM = 64, BN = 64, BK = 16;
    __shared__ float As[BK][BM + 1];
    __shared__ float Bs[BK][BN + 1];

    const int m0 = blockIdx.y * BM;
    const int n0 = blockIdx.x * BN;
    const int tid = threadIdx.x;
    const int tx = tid & 15, ty = tid >> 4;

    float acc[4][4] = {};

    for (int k0 = 0; k0 < FIN; k0 += BK) {
        #pragma unroll
        for (int i = 0; i < 4; i++) {
            int idx = tid + i * 256;
            int kk = idx & 15, mm = idx >> 4;
            As[kk][mm] = X[(size_t)(m0 + mm) * FIN + k0 + kk];
        }
        #pragma unroll
        for (int i = 0; i < 4; i++) {
            int idx = tid + i * 256;
            int nn = idx & 63, kk = idx >> 6;
            Bs[kk][nn] = W[(size_t)(k0 + kk) * FOUT + n0 + nn];
        }
        __syncthreads();
        #pragma unroll
        for (int kk = 0; kk < BK; kk++) {
            float a[4], b[4];
            #pragma unroll
            for (int i = 0; i < 4; i++) a[i] = As[kk][ty * 4 + i];
            #pragma unroll
            for (int j = 0; j < 4; j++) b[j] = Bs[kk][tx * 4 + j];
            #pragma unroll
            for (int i = 0; i < 4; i++)
                #pragma unroll
                for (int j = 0; j < 4; j++)
                    acc[i][j] = fmaf(a[i], b[j], acc[i][j]);
        }
        __syncthreads();
    }
    #pragma unroll
    for (int i = 0; i < 4; i++)
        #pragma unroll
        for (int j = 0; j < 4; j++)
            d_h[(size_t)(m0 + ty * 4 + i) * FOUT + n0 + tx * 4 + j] = acc[i][j];
}

// ---------------- f1/f2: per-row dot with a1/a2 ------------------------------
__global__ void k_f12(const float* __restrict__ a)
{
    int row  = (blockIdx.x * blockDim.x + threadIdx.x) >> 5;
    int lane = threadIdx.x & 31;
    if (row >= MTOT) return;
    const float* hr = d_h + (size_t)row * FOUT;
    float s1 = 0.f, s2 = 0.f;
    for (int k = lane; k < FOUT; k += 32) {
        float hv = hr[k];
        s1 = fmaf(hv, a[k], s1);
        s2 = fmaf(hv, a[FOUT + k], s2);
    }
    #pragma unroll
    for (int o = 16; o; o >>= 1) {
        s1 += __shfl_xor_sync(0xffffffffu, s1, o);
        s2 += __shfl_xor_sync(0xffffffffu, s2, o);
    }
    if (lane == 0) { d_f1[row] = s1; d_f2[row] = s2; }
}

// ---------------- attention row: masked leakyrelu + softmax numerators -------
// One block (256 thr) per (b,i) row. Stores unnormalized exp(e-m); 1/sum kept
// separately and folded into the agg-GEMM epilogue.
__global__ void k_att(const int* __restrict__ adj)
{
    const int row = blockIdx.x;           // 0..16383
    const int b   = row >> 10;
    const int tid = threadIdx.x;

    __shared__ float sh[NN];
    __shared__ float red[256];

    const float f1i = d_f1[row];
    const int*   arow = adj + (size_t)row * NN;
    const float* f2b  = d_f2 + b * NN;

    float lmax = -INFINITY;
    for (int j = tid; j < NN; j += 256) {
        float e = f1i + f2b[j];
        e = e > 0.f ? e : ALPHA_SLOPE * e;
        e = (arow[j] > 0) ? e : NEG_INF_F;
        sh[j] = e;
        lmax = fmaxf(lmax, e);
    }
    red[tid] = lmax;
    __syncthreads();
    for (int s = 128; s; s >>= 1) {
        if (tid < s) red[tid] = fmaxf(red[tid], red[tid + s]);
        __syncthreads();
    }
    const float m = red[0];
    __syncthreads();

    float lsum = 0.f;
    float* prow = d_att + (size_t)row * NN;
    for (int j = tid; j < NN; j += 256) {
        float p = __expf(sh[j] - m);
        prow[j] = p;
        lsum += p;
    }
    red[tid] = lsum;
    __syncthreads();
    for (int s = 128; s; s >>= 1) {
        if (tid < s) red[tid] += red[tid + s];
        __syncthreads();
    }
    if (tid == 0) d_inv[row] = 1.f / red[0];
}

// ---------------- GEMM 2: agg[b] = softmax(att[b]) @ h[b] --------------------
// Per-batch M=1024, K=1024, N=512; epilogue scales row by d_inv.
__global__ void k_gemm_agg()
{
    const int BM = 64, BN = 64, BK = 16;
    __shared__ float As[BK][BM + 1];
    __shared__ float Bs[BK][BN + 1];

    const int b  = blockIdx.z;
    const float* A  = d_att + (size_t)b * NN * NN;
    const float* Bm = d_h   + (size_t)b * NN * FOUT;
    float*       C  = d_agg + (size_t)b * NN * FOUT;

    const int m0 = blockIdx.y * BM;
    const int n0 = blockIdx.x * BN;
    const int tid = threadIdx.x;
    const int tx = tid & 15, ty = tid >> 4;

    float acc[4][4] = {};

    for (int k0 = 0; k0 < NN; k0 += BK) {
        #pragma unroll
        for (int i = 0; i < 4; i++) {
            int idx = tid + i * 256;
            int kk = idx & 15, mm = idx >> 4;
            As[kk][mm] = A[(size_t)(m0 + mm) * NN + k0 + kk];
        }
        #pragma unroll
        for (int i = 0; i < 4; i++) {
            int idx = tid + i * 256;
            int nn = idx & 63, kk = idx >> 6;
            Bs[kk][nn] = Bm[(size_t)(k0 + kk) * FOUT + n0 + nn];
        }
        __syncthreads();
        #pragma unroll
        for (int kk = 0; kk < BK; kk++) {
            float a[4], bb[4];
            #pragma unroll
            for (int i = 0; i < 4; i++) a[i] = As[kk][ty * 4 + i];
            #pragma unroll
            for (int j = 0; j < 4; j++) bb[j] = Bs[kk][tx * 4 + j];
            #pragma unroll
            for (int i = 0; i < 4; i++)
                #pragma unroll
                for (int j = 0; j < 4; j++)
                    acc[i][j] = fmaf(a[i], bb[j], acc[i][j]);
        }
        __syncthreads();
    }
    #pragma unroll
    for (int i = 0; i < 4; i++) {
        float sc = d_inv[b * NN + m0 + ty * 4 + i];
        #pragma unroll
        for (int j = 0; j < 4; j++)
            C[(size_t)(m0 + ty * 4 + i) * FOUT + n0 + tx * 4 + j] = acc[i][j] * sc;
    }
}

// ---------------- GEMM 3: out = elu([agg,h] @ fc_w^T + fc_b) -----------------
// M=16384, K=1024 (first 512 from agg, last 512 from h), N=512.
// B[k][n] = fc_w[n*1024 + k] (fc_w is [512, 1024] row-major).
__global__ void k_gemm_out(const float* __restrict__ FCW,
                           const float* __restrict__ FCB,
                           float* __restrict__ OUT)
{
    const int BM = 64, BN = 64, BK = 16;
    __shared__ float As[BK][BM + 1];
    __shared__ float Bs[BK][BN + 1];

    const int m0 = blockIdx.y * BM;
    const int n0 = blockIdx.x * BN;
    const int tid = threadIdx.x;
    const int tx = tid & 15, ty = tid >> 4;

    float acc[4][4] = {};

    for (int k0 = 0; k0 < 2 * FOUT; k0 += BK) {
        const float* Abase = (k0 < FOUT) ? (d_agg + k0) : (d_h + (k0 - FOUT));
        #pragma unroll
        for (int i = 0; i < 4; i++) {
            int idx = tid + i * 256;
            int kk = idx & 15, mm = idx >> 4;
            As[kk][mm] = Abase[(size_t)(m0 + mm) * FOUT + kk];
        }
        // B tile: fc_w rows are contiguous in k → map kk fastest for coalescing
        #pragma unroll
        for (int i = 0; i < 4; i++) {
            int idx = tid + i * 256;
            int kk = idx & 15, nn = idx >> 4;
            Bs[kk][nn] = FCW[(size_t)(n0 + nn) * (2 * FOUT) + k0 + kk];
        }
        __syncthreads();
        #pragma unroll
        for (int kk = 0; kk < BK; kk++) {
            float a[4], bb[4];
            #pragma unroll
            for (int i = 0; i < 4; i++) a[i] = As[kk][ty * 4 + i];
            #pragma unroll
            for (int j = 0; j < 4; j++) bb[j] = Bs[kk][tx * 4 + j];
            #pragma unroll
            for (int i = 0; i < 4; i++)
                #pragma unroll
                for (int j = 0; j < 4; j++)
                    acc[i][j] = fmaf(a[i], bb[j], acc[i][j]);
        }
        __syncthreads();
    }
    #pragma unroll
    for (int i = 0; i < 4; i++)
        #pragma unroll
        for (int j = 0; j < 4; j++) {
            int n = n0 + tx * 4 + j;
            float v = acc[i][j] + FCB[n];
            v = (v > 0.f) ? v : expm1f(v);   // elu, alpha=1
            OUT[(size_t)(m0 + ty * 4 + i) * FOUT + n] = v;
        }
}

// ---------------- launch -----------------------------------------------------
extern "C" void kernel_launch(void* const* d_in, const int* in_sizes, int n_in,
                              void* d_out, int out_size)
{
    const float* x   = (const float*)d_in[0];
    const int*   adj = (const int*)  d_in[1];
    const float* W   = (const float*)d_in[2];
    const float* a   = (const float*)d_in[3];
    const float* fcw = (const float*)d_in[4];
    const float* fcb = (const float*)d_in[5];
    float* out = (float*)d_out;

    // 1) h = x @ W
    k_gemm_h<<<dim3(FOUT / 64, MTOT / 64), 256>>>(x, W);
    // 2) f1, f2
    k_f12<<<(MTOT * 32) / 256, 256>>>(a);
    // 3) attention numerators + inverse row sums
    k_att<<<MTOT, 256>>>(adj);
    // 4) agg = softmax(att) @ h   (scale folded into epilogue)
    k_gemm_agg<<<dim3(FOUT / 64, NN / 64, BB), 256>>>();
    // 5) out = elu([agg, h] @ fc_w^T + fc_b)
    k_gemm_out<<<dim3(FOUT / 64, MTOT / 64), 256>>>(fcw, fcb, out);
}

// round 3
// speedup vs baseline: 2.7471x; 2.7471x over previous
#include <cuda_runtime.h>
#include <cuda_bf16.h>
#include <math.h>
#include <stdint.h>

#define ALPHA_SLOPE 0.2f
#define NEG_INF_F   -9000000000000000.0f

#define BB    16
#define NN    1024
#define FIN   1024
#define FOUT  512
#define MTOT  (BB*NN)        // 16384

// ---------------- scratch (static device globals) ---------------------------
__device__ __nv_bfloat16 d_x_hi [(size_t)MTOT * FIN];
__device__ __nv_bfloat16 d_x_lo [(size_t)MTOT * FIN];
__device__ __nv_bfloat16 d_wt_hi[(size_t)FOUT * FIN];      // W^T [512][1024]
__device__ __nv_bfloat16 d_wt_lo[(size_t)FOUT * FIN];
__device__ __nv_bfloat16 d_fcw_hi[(size_t)FOUT * 2 * FOUT];
__device__ __nv_bfloat16 d_fcw_lo[(size_t)FOUT * 2 * FOUT];
__device__ __nv_bfloat16 d_h_hi [(size_t)MTOT * FOUT];
__device__ __nv_bfloat16 d_h_lo [(size_t)MTOT * FOUT];
__device__ __nv_bfloat16 d_ht_hi[(size_t)BB * FOUT * NN];  // h^T per batch [512][1024]
__device__ __nv_bfloat16 d_ht_lo[(size_t)BB * FOUT * NN];
__device__ __nv_bfloat16 d_att_hi[(size_t)MTOT * NN];
__device__ __nv_bfloat16 d_att_lo[(size_t)MTOT * NN];
__device__ __nv_bfloat16 d_agg_hi[(size_t)MTOT * FOUT];
__device__ __nv_bfloat16 d_agg_lo[(size_t)MTOT * FOUT];
__device__ float d_f1 [MTOT];
__device__ float d_f2 [MTOT];
__device__ float d_inv[MTOT];

// ---------------- helpers ----------------------------------------------------
__device__ __forceinline__ uint32_t smem_u32(const void* p) {
    uint32_t a;
    asm("{ .reg .u64 t; cvta.to.shared.u64 t, %1; cvt.u32.u64 %0, t; }" : "=r"(a) : "l"(p));
    return a;
}
__device__ __forceinline__ void cp16(uint32_t s, const void* g) {
    asm volatile("cp.async.cg.shared.global [%0], [%1], 16;" :: "r"(s), "l"(g));
}
__device__ __forceinline__ void ldsm4(uint32_t* r, uint32_t addr) {
    asm volatile("ldmatrix.sync.aligned.m8n8.x4.shared.b16 {%0,%1,%2,%3}, [%4];"
        : "=r"(r[0]), "=r"(r[1]), "=r"(r[2]), "=r"(r[3]) : "r"(addr));
}
__device__ __forceinline__ void ldsm2(uint32_t* r, uint32_t addr) {
    asm volatile("ldmatrix.sync.aligned.m8n8.x2.shared.b16 {%0,%1}, [%2];"
        : "=r"(r[0]), "=r"(r[1]) : "r"(addr));
}
__device__ __forceinline__ void mma16816(float* c, const uint32_t* a, const uint32_t* b) {
    asm volatile("mma.sync.aligned.m16n8k16.row.col.f32.bf16.bf16.f32 "
        "{%0,%1,%2,%3}, {%4,%5,%6,%7}, {%8,%9}, {%0,%1,%2,%3};"
        : "+f"(c[0]), "+f"(c[1]), "+f"(c[2]), "+f"(c[3])
        : "r"(a[0]), "r"(a[1]), "r"(a[2]), "r"(a[3]), "r"(b[0]), "r"(b[1]));
}

// ---------------- fp32 -> bf16 hi/lo split ----------------------------------
__device__ __forceinline__ void split1(float v, __nv_bfloat16& h, __nv_bfloat16& l) {
    h = __float2bfloat16(v);
    l = __float2bfloat16(v - __bfloat162float(h));
}
__device__ __forceinline__ void split_pack(float v0, float v1, unsigned& h2, unsigned& l2) {
    __nv_bfloat16 h0, h1, l0, l1;
    split1(v0, h0, l0); split1(v1, h1, l1);
    h2 = ((unsigned)__bfloat16_as_ushort(h1) << 16) | __bfloat16_as_ushort(h0);
    l2 = ((unsigned)__bfloat16_as_ushort(l1) << 16) | __bfloat16_as_ushort(l0);
}

// ---------------- conversion kernels -----------------------------------------
__global__ void k_cvt_pair(const float* __restrict__ src, __nv_bfloat16* __restrict__ hi,
                           __nv_bfloat16* __restrict__ lo, int n2)
{
    int i = blockIdx.x * blockDim.x + threadIdx.x;
    if (i >= n2) return;
    float2 v = ((const float2*)src)[i];
    unsigned h2, l2; split_pack(v.x, v.y, h2, l2);
    ((unsigned*)hi)[i] = h2; ((unsigned*)lo)[i] = l2;
}

__global__ void k_cvt_wt(const float* __restrict__ W)   // W[1024][512] -> Wt[512][1024]
{
    int i = blockIdx.x * blockDim.x + threadIdx.x;       // 524288
    int n = i >> 10, k = i & 1023;
    float v = W[(size_t)k * FOUT + n];
    split1(v, d_wt_hi[i], d_wt_lo[i]);
}

// ---------------- transpose h -> h^T (per batch) ------------------------------
__global__ void k_tr()
{
    __shared__ __nv_bfloat16 t[32][33];
    const int z = blockIdx.z;
    const int b = z >> 1;
    const __nv_bfloat16* src = (z & 1) ? d_h_lo : d_h_hi;
    __nv_bfloat16*       dst = (z & 1) ? d_ht_lo : d_ht_hi;
    const int f0 = blockIdx.x * 32, n0 = blockIdx.y * 32;
    const int tx = threadIdx.x, ty = threadIdx.y;   // (32,8)
    #pragma unroll
    for (int i = 0; i < 4; i++) {
        int n = n0 + ty + i * 8;
        t[ty + i * 8][tx] = src[(size_t)(b * NN + n) * FOUT + f0 + tx];
    }
    __syncthreads();
    #pragma unroll
    for (int i = 0; i < 4; i++) {
        int f = f0 + ty + i * 8;
        dst[(size_t)(b * FOUT + f) * NN + n0 + tx] = t[tx][ty + i * 8];
    }
}

// ---------------- f1/f2 ------------------------------------------------------
__global__ void k_f12(const float* __restrict__ a)
{
    int row  = (blockIdx.x * blockDim.x + threadIdx.x) >> 5;
    int lane = threadIdx.x & 31;
    if (row >= MTOT) return;
    const __nv_bfloat16* hh = d_h_hi + (size_t)row * FOUT;
    const __nv_bfloat16* hl = d_h_lo + (size_t)row * FOUT;
    float s1 = 0.f, s2 = 0.f;
    for (int k = lane; k < FOUT; k += 32) {
        float hv = __bfloat162float(hh[k]) + __bfloat162float(hl[k]);
        s1 = fmaf(hv, a[k], s1);
        s2 = fmaf(hv, a[FOUT + k], s2);
    }
    #pragma unroll
    for (int o = 16; o; o >>= 1) {
        s1 += __shfl_xor_sync(0xffffffffu, s1, o);
        s2 += __shfl_xor_sync(0xffffffffu, s2, o);
    }
    if (lane == 0) { d_f1[row] = s1; d_f2[row] = s2; }
}

// ---------------- attention numerators (bf16 hi/lo) + 1/rowsum ---------------
__global__ void k_att(const int* __restrict__ adj)
{
    const int row = blockIdx.x;
    const int b   = row >> 10;
    const int tid = threadIdx.x;

    __shared__ float sh[NN];
    __shared__ float red[256];

    const float f1i = d_f1[row];
    const int*   arow = adj + (size_t)row * NN;
    const float* f2b  = d_f2 + b * NN;

    float lmax = -INFINITY;
    for (int j = tid; j < NN; j += 256) {
        float e = f1i + f2b[j];
        e = e > 0.f ? e : ALPHA_SLOPE * e;
        e = (arow[j] > 0) ? e : NEG_INF_F;
        sh[j] = e;
        lmax = fmaxf(lmax, e);
    }
    red[tid] = lmax;
    __syncthreads();
    for (int s = 128; s; s >>= 1) {
        if (tid < s) red[tid] = fmaxf(red[tid], red[tid + s]);
        __syncthreads();
    }
    const float m = red[0];
    __syncthreads();

    float lsum = 0.f;
    __nv_bfloat16* ph = d_att_hi + (size_t)row * NN;
    __nv_bfloat16* pl = d_att_lo + (size_t)row * NN;
    for (int j = tid; j < NN; j += 256) {
        float p = __expf(sh[j] - m);
        __nv_bfloat16 hh, ll; split1(p, hh, ll);
        ph[j] = hh; pl[j] = ll;
        lsum += p;
    }
    red[tid] = lsum;
    __syncthreads();
    for (int s = 128; s; s >>= 1) {
        if (tid < s) red[tid] += red[tid + s];
        __syncthreads();
    }
    if (tid == 0) d_inv[row] = 1.f / red[0];
}

// ---------------- mma.sync GEMM: 128x128 tile, BK=32, double-buffered --------
// smem per stage: 4 tiles (Ah, Al, Bh, Bl), each 128 rows x 40 cols bf16 = 10240 B
#define ROWB     80                    // (32+8)*2 bytes per padded row
#define TILE_B   10240
#define STAGE_B  40960
#define SM_BYTES (2 * STAGE_B)         // 81920

template<int MODE>
__global__ __launch_bounds__(256, 1)
void k_tc(const float* __restrict__ fcb, float* __restrict__ outp)
{
    extern __shared__ char smem[];
    const uint32_t sb = smem_u32(smem);
    const int tid = threadIdx.x;
    const int wid = tid >> 5, lane = tid & 31;
    const int wm = wid & 1, wn = wid >> 1;       // warp tile: 64 (m) x 32 (n)

    const int n0 = blockIdx.x * 128;
    const int m0 = blockIdx.y * 128;             // local row for MODE 2, global else
    const int b  = (MODE == 2) ? blockIdx.z : (m0 >> 10);

    float acc[4][4][4] = {};

    const int NIT = 32;                          // K = 1024, BK = 32

    auto issue = [&](int c) {
        const __nv_bfloat16 *Ah, *Al, *Bh, *Bl;
        int lda, ldb;
        if (MODE == 1) {
            lda = FIN; ldb = FIN;
            size_t ao = (size_t)m0 * FIN + c * 32;
            size_t bo = (size_t)n0 * FIN + c * 32;
            Ah = d_x_hi + ao;  Al = d_x_lo + ao;
            Bh = d_wt_hi + bo; Bl = d_wt_lo + bo;
        } else if (MODE == 2) {
            lda = NN; ldb = NN;
            size_t ao = (size_t)b * NN * NN + (size_t)m0 * NN + c * 32;
            size_t bo = (size_t)b * FOUT * NN + (size_t)n0 * NN + c * 32;
            Ah = d_att_hi + ao; Al = d_att_lo + ao;
            Bh = d_ht_hi + bo;  Bl = d_ht_lo + bo;
        } else {
            lda = FOUT; ldb = 2 * FOUT;
            size_t ao;
            if (c < 16) { ao = (size_t)m0 * FOUT + c * 32;        Ah = d_agg_hi + ao; Al = d_agg_lo + ao; }
            else        { ao = (size_t)m0 * FOUT + (c - 16) * 32; Ah = d_h_hi + ao;   Al = d_h_lo + ao; }
            size_t bo = (size_t)n0 * (2 * FOUT) + c * 32;
            Bh = d_fcw_hi + bo; Bl = d_fcw_lo + bo;
        }
        const uint32_t st = sb + (c & 1) * STAGE_B;
        #pragma unroll
        for (int i = 0; i < 2; i++) {
            int idx = tid + i * 256;
            int row = idx >> 2, seg = idx & 3;
            uint32_t so = row * ROWB + seg * 16;
            cp16(st + so,              Ah + (size_t)row * lda + seg * 8);
            cp16(st + TILE_B + so,     Al + (size_t)row * lda + seg * 8);
            cp16(st + 2 * TILE_B + so, Bh + (size_t)row * ldb + seg * 8);
            cp16(st + 3 * TILE_B + so, Bl + (size_t)row * ldb + seg * 8);
        }
        asm volatile("cp.async.commit_group;" ::: "memory");
    };

    issue(0);
    for (int c = 0; c < NIT; c++) {
        if (c + 1 < NIT) {
            issue(c + 1);
            asm volatile("cp.async.wait_group 1;" ::: "memory");
        } else {
            asm volatile("cp.async.wait_group 0;" ::: "memory");
        }
        __syncthreads();

        const uint32_t base = sb + (c & 1) * STAGE_B;
        #pragma unroll
        for (int ks = 0; ks < 2; ks++) {
            const int kb = ks * 32;               // 16 elements * 2B
            uint32_t ah[4][4], al[4][4], bh[4][2], bl[4][2];
            #pragma unroll
            for (int mt = 0; mt < 4; mt++) {
                uint32_t ra = base + (wm * 64 + mt * 16 + (lane & 15)) * ROWB + kb + (lane >> 4) * 16;
                ldsm4(ah[mt], ra);
                ldsm4(al[mt], ra + TILE_B);
            }
            #pragma unroll
            for (int nt = 0; nt < 4; nt++) {
                uint32_t rb = base + 2 * TILE_B + (wn * 32 + nt * 8 + (lane & 7)) * ROWB + kb + ((lane >> 3) & 1) * 16;
                ldsm2(bh[nt], rb);
                ldsm2(bl[nt], rb + TILE_B);
            }
            #pragma unroll
            for (int mt = 0; mt < 4; mt++)
                #pragma unroll
                for (int nt = 0; nt < 4; nt++) {
                    mma16816(acc[mt][nt], ah[mt], bh[nt]);
                    mma16816(acc[mt][nt], ah[mt], bl[nt]);
                    mma16816(acc[mt][nt], al[mt], bh[nt]);
                }
        }
        __syncthreads();
    }

    // ---------------- epilogue: direct fragment stores ----------------
    const int g = lane >> 2, tig = lane & 3;
    #pragma unroll
    for (int mt = 0; mt < 4; mt++) {
        const int lr0 = wm * 64 + mt * 16 + g;
        const int lr1 = lr0 + 8;
        float s0 = 1.f, s1 = 1.f;
        if (MODE == 2) {
            s0 = d_inv[b * NN + m0 + lr0];
            s1 = d_inv[b * NN + m0 + lr1];
        }
        #pragma unroll
        for (int nt = 0; nt < 4; nt++) {
            float* c = acc[mt][nt];
            const int ncol = n0 + wn * 32 + nt * 8 + tig * 2;
            if (MODE == 1) {
                unsigned h2, l2;
                split_pack(c[0], c[1], h2, l2);
                size_t o = (size_t)(m0 + lr0) * FOUT + ncol;
                *(unsigned*)(d_h_hi + o) = h2; *(unsigned*)(d_h_lo + o) = l2;
                split_pack(c[2], c[3], h2, l2);
                o = (size_t)(m0 + lr1) * FOUT + ncol;
                *(unsigned*)(d_h_hi + o) = h2; *(unsigned*)(d_h_lo + o) = l2;
            } else if (MODE == 2) {
                unsigned h2, l2;
                split_pack(c[0] * s0, c[1] * s0, h2, l2);
                size_t o = (size_t)(b * NN + m0 + lr0) * FOUT + ncol;
                *(unsigned*)(d_agg_hi + o) = h2; *(unsigned*)(d_agg_lo + o) = l2;
                split_pack(c[2] * s1, c[3] * s1, h2, l2);
                o = (size_t)(b * NN + m0 + lr1) * FOUT + ncol;
                *(unsigned*)(d_agg_hi + o) = h2; *(unsigned*)(d_agg_lo + o) = l2;
            } else {
                float b0 = fcb[ncol], b1 = fcb[ncol + 1];
                float v0 = c[0] + b0, v1 = c[1] + b1;
                v0 = v0 > 0.f ? v0 : expm1f(v0);
                v1 = v1 > 0.f ? v1 : expm1f(v1);
                *(float2*)(outp + (size_t)(m0 + lr0) * FOUT + ncol) = make_float2(v0, v1);
                float v2 = c[2] + b0, v3 = c[3] + b1;
                v2 = v2 > 0.f ? v2 : expm1f(v2);
                v3 = v3 > 0.f ? v3 : expm1f(v3);
                *(float2*)(outp + (size_t)(m0 + lr1) * FOUT + ncol) = make_float2(v2, v3);
            }
        }
    }
}

// ---------------- launch -----------------------------------------------------
extern "C" void kernel_launch(void* const* d_in, const int* in_sizes, int n_in,
                              void* d_out, int out_size)
{
    const float* x   = (const float*)d_in[0];
    const int*   adj = (const int*)  d_in[1];
    const float* W   = (const float*)d_in[2];
    const float* a   = (const float*)d_in[3];
    const float* fcw = (const float*)d_in[4];
    const float* fcb = (const float*)d_in[5];
    float* out = (float*)d_out;

    cudaFuncSetAttribute(k_tc<1>, cudaFuncAttributeMaxDynamicSharedMemorySize, SM_BYTES);
    cudaFuncSetAttribute(k_tc<2>, cudaFuncAttributeMaxDynamicSharedMemorySize, SM_BYTES);
    cudaFuncSetAttribute(k_tc<3>, cudaFuncAttributeMaxDynamicSharedMemorySize, SM_BYTES);

    __nv_bfloat16 *xh, *xl, *fh, *fl;
    cudaGetSymbolAddress((void**)&xh, d_x_hi);
    cudaGetSymbolAddress((void**)&xl, d_x_lo);
    cudaGetSymbolAddress((void**)&fh, d_fcw_hi);
    cudaGetSymbolAddress((void**)&fl, d_fcw_lo);

    // conversions
    k_cvt_pair<<<(MTOT * FIN / 2 + 255) / 256, 256>>>(x, xh, xl, MTOT * FIN / 2);
    k_cvt_wt  <<<(FOUT * FIN + 255) / 256, 256>>>(W);
    k_cvt_pair<<<(FOUT * 2 * FOUT / 2 + 255) / 256, 256>>>(fcw, fh, fl, FOUT * 2 * FOUT / 2);

    // 1) h = x @ W
    k_tc<1><<<dim3(FOUT / 128, MTOT / 128), 256, SM_BYTES>>>(nullptr, nullptr);
    // 1b) h^T per batch (hi & lo)
    k_tr<<<dim3(FOUT / 32, NN / 32, BB * 2), dim3(32, 8)>>>();
    // 2) f1, f2
    k_f12<<<(MTOT * 32) / 256, 256>>>(a);
    // 3) attention numerators + inverse row sums
    k_att<<<MTOT, 256>>>(adj);
    // 4) agg = softmax(att) @ h
    k_tc<2><<<dim3(FOUT / 128, NN / 128, BB), 256, SM_BYTES>>>(nullptr, nullptr);
    // 5) out = elu([agg, h] @ fc_w^T + fc_b)
    k_tc<3><<<dim3(FOUT / 128, MTOT / 128), 256, SM_BYTES>>>(fcb, out);
}

// round 4
// speedup vs baseline: 3.0318x; 1.1036x over previous
#include <cuda_runtime.h>
#include <cuda_bf16.h>
#include <math.h>
#include <stdint.h>

#define ALPHA_SLOPE 0.2f
#define NEG_INF_F   -9000000000000000.0f

#define BB    16
#define NN    1024
#define FIN   1024
#define FOUT  512
#define MTOT  (BB*NN)        // 16384

// ---------------- scratch (static device globals) ---------------------------
__device__ __nv_bfloat16 d_x_hi [(size_t)MTOT * FIN];
__device__ __nv_bfloat16 d_x_lo [(size_t)MTOT * FIN];
__device__ __nv_bfloat16 d_wt_hi[(size_t)FOUT * FIN];      // W^T [512][1024]
__device__ __nv_bfloat16 d_wt_lo[(size_t)FOUT * FIN];
__device__ __nv_bfloat16 d_fcw_hi[(size_t)FOUT * 2 * FOUT];
__device__ __nv_bfloat16 d_fcw_lo[(size_t)FOUT * 2 * FOUT];
__device__ __nv_bfloat16 d_h_hi [(size_t)MTOT * FOUT];
__device__ __nv_bfloat16 d_h_lo [(size_t)MTOT * FOUT];
__device__ __nv_bfloat16 d_ht_hi[(size_t)BB * FOUT * NN];  // h^T per batch [512][1024]
__device__ __nv_bfloat16 d_ht_lo[(size_t)BB * FOUT * NN];
__device__ __nv_bfloat16 d_att_hi[(size_t)MTOT * NN];
__device__ __nv_bfloat16 d_att_lo[(size_t)MTOT * NN];
__device__ __nv_bfloat16 d_agg_hi[(size_t)MTOT * FOUT];
__device__ __nv_bfloat16 d_agg_lo[(size_t)MTOT * FOUT];
__device__ float d_f1 [MTOT];
__device__ float d_f2 [MTOT];
__device__ float d_inv[MTOT];

// ---------------- helpers ----------------------------------------------------
__device__ __forceinline__ uint32_t smem_u32(const void* p) {
    uint32_t a;
    asm("{ .reg .u64 t; cvta.to.shared.u64 t, %1; cvt.u32.u64 %0, t; }" : "=r"(a) : "l"(p));
    return a;
}
__device__ __forceinline__ void cp16(uint32_t s, const void* g) {
    asm volatile("cp.async.cg.shared.global [%0], [%1], 16;" :: "r"(s), "l"(g));
}
__device__ __forceinline__ void ldsm4(uint32_t* r, uint32_t addr) {
    asm volatile("ldmatrix.sync.aligned.m8n8.x4.shared.b16 {%0,%1,%2,%3}, [%4];"
        : "=r"(r[0]), "=r"(r[1]), "=r"(r[2]), "=r"(r[3]) : "r"(addr));
}
__device__ __forceinline__ void ldsm2(uint32_t* r, uint32_t addr) {
    asm volatile("ldmatrix.sync.aligned.m8n8.x2.shared.b16 {%0,%1}, [%2];"
        : "=r"(r[0]), "=r"(r[1]) : "r"(addr));
}
__device__ __forceinline__ void mma16816(float* c, const uint32_t* a, const uint32_t* b) {
    asm volatile("mma.sync.aligned.m16n8k16.row.col.f32.bf16.bf16.f32 "
        "{%0,%1,%2,%3}, {%4,%5,%6,%7}, {%8,%9}, {%0,%1,%2,%3};"
        : "+f"(c[0]), "+f"(c[1]), "+f"(c[2]), "+f"(c[3])
        : "r"(a[0]), "r"(a[1]), "r"(a[2]), "r"(a[3]), "r"(b[0]), "r"(b[1]));
}

// ---------------- fp32 -> bf16 hi/lo split ----------------------------------
__device__ __forceinline__ void split1(float v, __nv_bfloat16& h, __nv_bfloat16& l) {
    h = __float2bfloat16(v);
    l = __float2bfloat16(v - __bfloat162float(h));
}
__device__ __forceinline__ void split_pack(float v0, float v1, unsigned& h2, unsigned& l2) {
    __nv_bfloat16 h0, h1, l0, l1;
    split1(v0, h0, l0); split1(v1, h1, l1);
    h2 = ((unsigned)__bfloat16_as_ushort(h1) << 16) | __bfloat16_as_ushort(h0);
    l2 = ((unsigned)__bfloat16_as_ushort(l1) << 16) | __bfloat16_as_ushort(l0);
}

// ---------------- conversion kernels -----------------------------------------
__global__ void k_cvt_pair(const float* __restrict__ src, __nv_bfloat16* __restrict__ hi,
                           __nv_bfloat16* __restrict__ lo, int n2)
{
    int i = blockIdx.x * blockDim.x + threadIdx.x;
    if (i >= n2) return;
    float2 v = ((const float2*)src)[i];
    unsigned h2, l2; split_pack(v.x, v.y, h2, l2);
    ((unsigned*)hi)[i] = h2; ((unsigned*)lo)[i] = l2;
}

__global__ void k_cvt_wt(const float* __restrict__ W)   // W[1024][512] -> Wt[512][1024]
{
    int i = blockIdx.x * blockDim.x + threadIdx.x;       // 524288
    int n = i >> 10, k = i & 1023;
    float v = W[(size_t)k * FOUT + n];
    split1(v, d_wt_hi[i], d_wt_lo[i]);
}

// ---------------- transpose h -> h^T (per batch) ------------------------------
__global__ void k_tr()
{
    __shared__ __nv_bfloat16 t[32][33];
    const int z = blockIdx.z;
    const int b = z >> 1;
    const __nv_bfloat16* src = (z & 1) ? d_h_lo : d_h_hi;
    __nv_bfloat16*       dst = (z & 1) ? d_ht_lo : d_ht_hi;
    const int f0 = blockIdx.x * 32, n0 = blockIdx.y * 32;
    const int tx = threadIdx.x, ty = threadIdx.y;   // (32,8)
    #pragma unroll
    for (int i = 0; i < 4; i++) {
        int n = n0 + ty + i * 8;
        t[ty + i * 8][tx] = src[(size_t)(b * NN + n) * FOUT + f0 + tx];
    }
    __syncthreads();
    #pragma unroll
    for (int i = 0; i < 4; i++) {
        int f = f0 + ty + i * 8;
        dst[(size_t)(b * FOUT + f) * NN + n0 + tx] = t[tx][ty + i * 8];
    }
}

// ---------------- f1/f2 ------------------------------------------------------
__global__ void k_f12(const float* __restrict__ a)
{
    int row  = (blockIdx.x * blockDim.x + threadIdx.x) >> 5;
    int lane = threadIdx.x & 31;
    if (row >= MTOT) return;
    const __nv_bfloat16* hh = d_h_hi + (size_t)row * FOUT;
    const __nv_bfloat16* hl = d_h_lo + (size_t)row * FOUT;
    float s1 = 0.f, s2 = 0.f;
    for (int k = lane; k < FOUT; k += 32) {
        float hv = __bfloat162float(hh[k]) + __bfloat162float(hl[k]);
        s1 = fmaf(hv, a[k], s1);
        s2 = fmaf(hv, a[FOUT + k], s2);
    }
    #pragma unroll
    for (int o = 16; o; o >>= 1) {
        s1 += __shfl_xor_sync(0xffffffffu, s1, o);
        s2 += __shfl_xor_sync(0xffffffffu, s2, o);
    }
    if (lane == 0) { d_f1[row] = s1; d_f2[row] = s2; }
}

// ---------------- attention numerators (bf16 hi/lo) + 1/rowsum ---------------
__global__ void k_att(const int* __restrict__ adj)
{
    const int row = blockIdx.x;
    const int b   = row >> 10;
    const int tid = threadIdx.x;

    __shared__ float sh[NN];
    __shared__ float red[256];

    const float f1i = d_f1[row];
    const int*   arow = adj + (size_t)row * NN;
    const float* f2b  = d_f2 + b * NN;

    float lmax = -INFINITY;
    for (int j = tid; j < NN; j += 256) {
        float e = f1i + f2b[j];
        e = e > 0.f ? e : ALPHA_SLOPE * e;
        e = (arow[j] > 0) ? e : NEG_INF_F;
        sh[j] = e;
        lmax = fmaxf(lmax, e);
    }
    red[tid] = lmax;
    __syncthreads();
    for (int s = 128; s; s >>= 1) {
        if (tid < s) red[tid] = fmaxf(red[tid], red[tid + s]);
        __syncthreads();
    }
    const float m = red[0];
    __syncthreads();

    float lsum = 0.f;
    __nv_bfloat16* ph = d_att_hi + (size_t)row * NN;
    __nv_bfloat16* pl = d_att_lo + (size_t)row * NN;
    for (int j = tid; j < NN; j += 256) {
        float p = __expf(sh[j] - m);
        __nv_bfloat16 hh, ll; split1(p, hh, ll);
        ph[j] = hh; pl[j] = ll;
        lsum += p;
    }
    red[tid] = lsum;
    __syncthreads();
    for (int s = 128; s; s >>= 1) {
        if (tid < s) red[tid] += red[tid + s];
        __syncthreads();
    }
    if (tid == 0) d_inv[row] = 1.f / red[0];
}

// ---------------- mma.sync GEMM: 128(M)x256(N) tile, BK=32, 512 thr ----------
// padded rows: 40 bf16 cols = 80 B. A tile (128 rows) = 10240 B; B tile (256) = 20480 B
#define ROWB     80
#define A_TILE_B 10240
#define B_TILE_B 20480
#define STAGE_B  61440                 // Ah, Al, Bh, Bl
#define SM_BYTES (2 * STAGE_B)         // 122880

template<int MODE>
__global__ __launch_bounds__(512, 1)
void k_tc(const float* __restrict__ fcb, float* __restrict__ outp)
{
    extern __shared__ char smem[];
    const uint32_t sb = smem_u32(smem);
    const int tid = threadIdx.x;
    const int wid = tid >> 5, lane = tid & 31;
    const int wm = wid & 1, wn = wid >> 1;       // 2 x 8 warp grid; warp tile 64m x 32n

    const int n0 = blockIdx.x * 256;
    const int m0 = blockIdx.y * 128;             // local row for MODE 2, global else
    const int b  = (MODE == 2) ? blockIdx.z : (m0 >> 10);

    float acc[4][4][4] = {};

    const int NIT = 32;                          // K = 1024, BK = 32

    auto issue = [&](int c) {
        const __nv_bfloat16 *Ah, *Al, *Bh, *Bl;
        int lda, ldb;
        if (MODE == 1) {
            lda = FIN; ldb = FIN;
            size_t ao = (size_t)m0 * FIN + c * 32;
            size_t bo = (size_t)n0 * FIN + c * 32;
            Ah = d_x_hi + ao;  Al = d_x_lo + ao;
            Bh = d_wt_hi + bo; Bl = d_wt_lo + bo;
        } else if (MODE == 2) {
            lda = NN; ldb = NN;
            size_t ao = (size_t)b * NN * NN + (size_t)m0 * NN + c * 32;
            size_t bo = (size_t)b * FOUT * NN + (size_t)n0 * NN + c * 32;
            Ah = d_att_hi + ao; Al = d_att_lo + ao;
            Bh = d_ht_hi + bo;  Bl = d_ht_lo + bo;
        } else {
            lda = FOUT; ldb = 2 * FOUT;
            size_t ao;
            if (c < 16) { ao = (size_t)m0 * FOUT + c * 32;        Ah = d_agg_hi + ao; Al = d_agg_lo + ao; }
            else        { ao = (size_t)m0 * FOUT + (c - 16) * 32; Ah = d_h_hi + ao;   Al = d_h_lo + ao; }
            size_t bo = (size_t)n0 * (2 * FOUT) + c * 32;
            Bh = d_fcw_hi + bo; Bl = d_fcw_lo + bo;
        }
        const uint32_t st = sb + (c & 1) * STAGE_B;
        // A tiles: 128 rows x 4 segs = 512 ops per tile; one per thread
        {
            int row = tid >> 2, seg = tid & 3;
            uint32_t so = row * ROWB + seg * 16;
            cp16(st + so,            Ah + (size_t)row * lda + seg * 8);
            cp16(st + A_TILE_B + so, Al + (size_t)row * lda + seg * 8);
        }
        // B tiles: 256 rows x 4 segs = 1024 ops per tile; two per thread
        #pragma unroll
        for (int i = 0; i < 2; i++) {
            int idx = tid + i * 512;
            int row = idx >> 2, seg = idx & 3;
            uint32_t so = 2 * A_TILE_B + row * ROWB + seg * 16;
            cp16(st + so,            Bh + (size_t)row * ldb + seg * 8);
            cp16(st + B_TILE_B + so, Bl + (size_t)row * ldb + seg * 8);
        }
        asm volatile("cp.async.commit_group;" ::: "memory");
    };

    issue(0);
    for (int c = 0; c < NIT; c++) {
        if (c + 1 < NIT) {
            issue(c + 1);
            asm volatile("cp.async.wait_group 1;" ::: "memory");
        } else {
            asm volatile("cp.async.wait_group 0;" ::: "memory");
        }
        __syncthreads();

        const uint32_t base = sb + (c & 1) * STAGE_B;
        #pragma unroll
        for (int ks = 0; ks < 2; ks++) {
            const int kb = ks * 32;               // 16 elements * 2B
            // load all B fragments first (16 regs live)
            uint32_t bh[4][2], bl[4][2];
            #pragma unroll
            for (int nt = 0; nt < 4; nt++) {
                uint32_t rb = base + 2 * A_TILE_B + (wn * 32 + nt * 8 + (lane & 7)) * ROWB
                            + kb + ((lane >> 3) & 1) * 16;
                ldsm2(bh[nt], rb);
                ldsm2(bl[nt], rb + B_TILE_B);
            }
            // stream A fragments per mt (8 regs live at a time)
            #pragma unroll
            for (int mt = 0; mt < 4; mt++) {
                uint32_t ah[4], al[4];
                uint32_t ra = base + (wm * 64 + mt * 16 + (lane & 15)) * ROWB + kb + (lane >> 4) * 16;
                ldsm4(ah, ra);
                ldsm4(al, ra + A_TILE_B);
                #pragma unroll
                for (int nt = 0; nt < 4; nt++) {
                    mma16816(acc[mt][nt], ah, bh[nt]);
                    mma16816(acc[mt][nt], ah, bl[nt]);
                    mma16816(acc[mt][nt], al, bh[nt]);
                }
            }
        }
        __syncthreads();
    }

    // ---------------- epilogue: direct fragment stores ----------------
    const int g = lane >> 2, tig = lane & 3;
    #pragma unroll
    for (int mt = 0; mt < 4; mt++) {
        const int lr0 = wm * 64 + mt * 16 + g;
        const int lr1 = lr0 + 8;
        float s0 = 1.f, s1 = 1.f;
        if (MODE == 2) {
            s0 = d_inv[b * NN + m0 + lr0];
            s1 = d_inv[b * NN + m0 + lr1];
        }
        #pragma unroll
        for (int nt = 0; nt < 4; nt++) {
            float* c = acc[mt][nt];
            const int ncol = n0 + wn * 32 + nt * 8 + tig * 2;
            if (MODE == 1) {
                unsigned h2, l2;
                split_pack(c[0], c[1], h2, l2);
                size_t o = (size_t)(m0 + lr0) * FOUT + ncol;
                *(unsigned*)(d_h_hi + o) = h2; *(unsigned*)(d_h_lo + o) = l2;
                split_pack(c[2], c[3], h2, l2);
                o = (size_t)(m0 + lr1) * FOUT + ncol;
                *(unsigned*)(d_h_hi + o) = h2; *(unsigned*)(d_h_lo + o) = l2;
            } else if (MODE == 2) {
                unsigned h2, l2;
                split_pack(c[0] * s0, c[1] * s0, h2, l2);
                size_t o = (size_t)(b * NN + m0 + lr0) * FOUT + ncol;
                *(unsigned*)(d_agg_hi + o) = h2; *(unsigned*)(d_agg_lo + o) = l2;
                split_pack(c[2] * s1, c[3] * s1, h2, l2);
                o = (size_t)(b * NN + m0 + lr1) * FOUT + ncol;
                *(unsigned*)(d_agg_hi + o) = h2; *(unsigned*)(d_agg_lo + o) = l2;
            } else {
                float b0 = fcb[ncol], b1 = fcb[ncol + 1];
                float v0 = c[0] + b0, v1 = c[1] + b1;
                v0 = v0 > 0.f ? v0 : expm1f(v0);
                v1 = v1 > 0.f ? v1 : expm1f(v1);
                *(float2*)(outp + (size_t)(m0 + lr0) * FOUT + ncol) = make_float2(v0, v1);
                float v2 = c[2] + b0, v3 = c[3] + b1;
                v2 = v2 > 0.f ? v2 : expm1f(v2);
                v3 = v3 > 0.f ? v3 : expm1f(v3);
                *(float2*)(outp + (size_t)(m0 + lr1) * FOUT + ncol) = make_float2(v2, v3);
            }
        }
    }
}

// ---------------- launch -----------------------------------------------------
extern "C" void kernel_launch(void* const* d_in, const int* in_sizes, int n_in,
                              void* d_out, int out_size)
{
    const float* x   = (const float*)d_in[0];
    const int*   adj = (const int*)  d_in[1];
    const float* W   = (const float*)d_in[2];
    const float* a   = (const float*)d_in[3];
    const float* fcw = (const float*)d_in[4];
    const float* fcb = (const float*)d_in[5];
    float* out = (float*)d_out;

    cudaFuncSetAttribute(k_tc<1>, cudaFuncAttributeMaxDynamicSharedMemorySize, SM_BYTES);
    cudaFuncSetAttribute(k_tc<2>, cudaFuncAttributeMaxDynamicSharedMemorySize, SM_BYTES);
    cudaFuncSetAttribute(k_tc<3>, cudaFuncAttributeMaxDynamicSharedMemorySize, SM_BYTES);

    __nv_bfloat16 *xh, *xl, *fh, *fl;
    cudaGetSymbolAddress((void**)&xh, d_x_hi);
    cudaGetSymbolAddress((void**)&xl, d_x_lo);
    cudaGetSymbolAddress((void**)&fh, d_fcw_hi);
    cudaGetSymbolAddress((void**)&fl, d_fcw_lo);

    // conversions
    k_cvt_pair<<<(MTOT * FIN / 2 + 255) / 256, 256>>>(x, xh, xl, MTOT * FIN / 2);
    k_cvt_wt  <<<(FOUT * FIN + 255) / 256, 256>>>(W);
    k_cvt_pair<<<(FOUT * 2 * FOUT / 2 + 255) / 256, 256>>>(fcw, fh, fl, FOUT * 2 * FOUT / 2);

    // 1) h = x @ W
    k_tc<1><<<dim3(FOUT / 256, MTOT / 128), 512, SM_BYTES>>>(nullptr, nullptr);
    // 1b) h^T per batch (hi & lo)
    k_tr<<<dim3(FOUT / 32, NN / 32, BB * 2), dim3(32, 8)>>>();
    // 2) f1, f2
    k_f12<<<(MTOT * 32) / 256, 256>>>(a);
    // 3) attention numerators + inverse row sums
    k_att<<<MTOT, 256>>>(adj);
    // 4) agg = softmax(att) @ h
    k_tc<2><<<dim3(FOUT / 256, NN / 128, BB), 512, SM_BYTES>>>(nullptr, nullptr);
    // 5) out = elu([agg, h] @ fc_w^T + fc_b)
    k_tc<3><<<dim3(FOUT / 256, MTOT / 128), 512, SM_BYTES>>>(fcb, out);
}

// round 5
// speedup vs baseline: 3.1472x; 1.0381x over previous
#include <cuda_runtime.h>
#include <cuda_bf16.h>
#include <math.h>
#include <stdint.h>

#define ALPHA_SLOPE 0.2f
#define NEG_INF_F   -9000000000000000.0f

#define BB    16
#define NN    1024
#define FIN   1024
#define FOUT  512
#define MTOT  (BB*NN)        // 16384

// ---------------- scratch (static device globals) ---------------------------
__device__ __nv_bfloat16 d_x_hi [(size_t)MTOT * FIN];
__device__ __nv_bfloat16 d_x_lo [(size_t)MTOT * FIN];
__device__ __nv_bfloat16 d_wt_hi[(size_t)FOUT * FIN];      // W^T [512][1024]
__device__ __nv_bfloat16 d_wt_lo[(size_t)FOUT * FIN];
__device__ __nv_bfloat16 d_fcw_hi[(size_t)FOUT * 2 * FOUT];
__device__ __nv_bfloat16 d_fcw_lo[(size_t)FOUT * 2 * FOUT];
__device__ __nv_bfloat16 d_h_hi [(size_t)MTOT * FOUT];
__device__ __nv_bfloat16 d_h_lo [(size_t)MTOT * FOUT];
__device__ __nv_bfloat16 d_ht_hi[(size_t)BB * FOUT * NN];  // h^T per batch [512][1024]
__device__ __nv_bfloat16 d_ht_lo[(size_t)BB * FOUT * NN];
__device__ __nv_bfloat16 d_att_hi[(size_t)MTOT * NN];
__device__ __nv_bfloat16 d_att_lo[(size_t)MTOT * NN];
__device__ __nv_bfloat16 d_agg_hi[(size_t)MTOT * FOUT];
__device__ __nv_bfloat16 d_agg_lo[(size_t)MTOT * FOUT];
__device__ float d_f1 [MTOT];
__device__ float d_f2 [MTOT];
__device__ float d_inv[MTOT];

// ---------------- helpers ----------------------------------------------------
__device__ __forceinline__ uint32_t smem_u32(const void* p) {
    uint32_t a;
    asm("{ .reg .u64 t; cvta.to.shared.u64 t, %1; cvt.u32.u64 %0, t; }" : "=r"(a) : "l"(p));
    return a;
}
__device__ __forceinline__ void cp16(uint32_t s, const void* g) {
    asm volatile("cp.async.cg.shared.global [%0], [%1], 16;" :: "r"(s), "l"(g));
}
__device__ __forceinline__ void ldsm4(uint32_t* r, uint32_t addr) {
    asm volatile("ldmatrix.sync.aligned.m8n8.x4.shared.b16 {%0,%1,%2,%3}, [%4];"
        : "=r"(r[0]), "=r"(r[1]), "=r"(r[2]), "=r"(r[3]) : "r"(addr));
}
__device__ __forceinline__ void ldsm2(uint32_t* r, uint32_t addr) {
    asm volatile("ldmatrix.sync.aligned.m8n8.x2.shared.b16 {%0,%1}, [%2];"
        : "=r"(r[0]), "=r"(r[1]) : "r"(addr));
}
__device__ __forceinline__ void mma16816(float* c, const uint32_t* a, const uint32_t* b) {
    asm volatile("mma.sync.aligned.m16n8k16.row.col.f32.bf16.bf16.f32 "
        "{%0,%1,%2,%3}, {%4,%5,%6,%7}, {%8,%9}, {%0,%1,%2,%3};"
        : "+f"(c[0]), "+f"(c[1]), "+f"(c[2]), "+f"(c[3])
        : "r"(a[0]), "r"(a[1]), "r"(a[2]), "r"(a[3]), "r"(b[0]), "r"(b[1]));
}

// ---------------- fp32 -> bf16 hi/lo split ----------------------------------
__device__ __forceinline__ void split1(float v, __nv_bfloat16& h, __nv_bfloat16& l) {
    h = __float2bfloat16(v);
    l = __float2bfloat16(v - __bfloat162float(h));
}
__device__ __forceinline__ void split_pack(float v0, float v1, unsigned& h2, unsigned& l2) {
    __nv_bfloat16 h0, h1, l0, l1;
    split1(v0, h0, l0); split1(v1, h1, l1);
    h2 = ((unsigned)__bfloat16_as_ushort(h1) << 16) | __bfloat16_as_ushort(h0);
    l2 = ((unsigned)__bfloat16_as_ushort(l1) << 16) | __bfloat16_as_ushort(l0);
}

// ---------------- conversion kernels -----------------------------------------
__global__ void k_cvt_pair(const float* __restrict__ src, __nv_bfloat16* __restrict__ hi,
                           __nv_bfloat16* __restrict__ lo, int n2)
{
    int i = blockIdx.x * blockDim.x + threadIdx.x;
    if (i >= n2) return;
    float2 v = ((const float2*)src)[i];
    unsigned h2, l2; split_pack(v.x, v.y, h2, l2);
    ((unsigned*)hi)[i] = h2; ((unsigned*)lo)[i] = l2;
}

__global__ void k_cvt_wt(const float* __restrict__ W)   // W[1024][512] -> Wt[512][1024]
{
    int i = blockIdx.x * blockDim.x + threadIdx.x;       // 524288
    int n = i >> 10, k = i & 1023;
    float v = W[(size_t)k * FOUT + n];
    split1(v, d_wt_hi[i], d_wt_lo[i]);
}

// ---------------- transpose h -> h^T (per batch) ------------------------------
__global__ void k_tr()
{
    __shared__ __nv_bfloat16 t[32][33];
    const int z = blockIdx.z;
    const int b = z >> 1;
    const __nv_bfloat16* src = (z & 1) ? d_h_lo : d_h_hi;
    __nv_bfloat16*       dst = (z & 1) ? d_ht_lo : d_ht_hi;
    const int f0 = blockIdx.x * 32, n0 = blockIdx.y * 32;
    const int tx = threadIdx.x, ty = threadIdx.y;   // (32,8)
    #pragma unroll
    for (int i = 0; i < 4; i++) {
        int n = n0 + ty + i * 8;
        t[ty + i * 8][tx] = src[(size_t)(b * NN + n) * FOUT + f0 + tx];
    }
    __syncthreads();
    #pragma unroll
    for (int i = 0; i < 4; i++) {
        int f = f0 + ty + i * 8;
        dst[(size_t)(b * FOUT + f) * NN + n0 + tx] = t[tx][ty + i * 8];
    }
}

// ---------------- f1/f2 ------------------------------------------------------
__global__ void k_f12(const float* __restrict__ a)
{
    int row  = (blockIdx.x * blockDim.x + threadIdx.x) >> 5;
    int lane = threadIdx.x & 31;
    if (row >= MTOT) return;
    const __nv_bfloat16* hh = d_h_hi + (size_t)row * FOUT;
    const __nv_bfloat16* hl = d_h_lo + (size_t)row * FOUT;
    float s1 = 0.f, s2 = 0.f;
    for (int k = lane; k < FOUT; k += 32) {
        float hv = __bfloat162float(hh[k]) + __bfloat162float(hl[k]);
        s1 = fmaf(hv, a[k], s1);
        s2 = fmaf(hv, a[FOUT + k], s2);
    }
    #pragma unroll
    for (int o = 16; o; o >>= 1) {
        s1 += __shfl_xor_sync(0xffffffffu, s1, o);
        s2 += __shfl_xor_sync(0xffffffffu, s2, o);
    }
    if (lane == 0) { d_f1[row] = s1; d_f2[row] = s2; }
}

// ---------------- attention numerators (bf16 hi/lo) + 1/rowsum ---------------
__global__ void k_att(const int* __restrict__ adj)
{
    const int row = blockIdx.x;
    const int b   = row >> 10;
    const int tid = threadIdx.x;

    __shared__ float sh[NN];
    __shared__ float red[256];

    const float f1i = d_f1[row];
    const int*   arow = adj + (size_t)row * NN;
    const float* f2b  = d_f2 + b * NN;

    float lmax = -INFINITY;
    for (int j = tid; j < NN; j += 256) {
        float e = f1i + f2b[j];
        e = e > 0.f ? e : ALPHA_SLOPE * e;
        e = (arow[j] > 0) ? e : NEG_INF_F;
        sh[j] = e;
        lmax = fmaxf(lmax, e);
    }
    red[tid] = lmax;
    __syncthreads();
    for (int s = 128; s; s >>= 1) {
        if (tid < s) red[tid] = fmaxf(red[tid], red[tid + s]);
        __syncthreads();
    }
    const float m = red[0];
    __syncthreads();

    float lsum = 0.f;
    __nv_bfloat16* ph = d_att_hi + (size_t)row * NN;
    __nv_bfloat16* pl = d_att_lo + (size_t)row * NN;
    for (int j = tid; j < NN; j += 256) {
        float p = __expf(sh[j] - m);
        __nv_bfloat16 hh, ll; split1(p, hh, ll);
        ph[j] = hh; pl[j] = ll;
        lsum += p;
    }
    red[tid] = lsum;
    __syncthreads();
    for (int s = 128; s; s >>= 1) {
        if (tid < s) red[tid] += red[tid + s];
        __syncthreads();
    }
    if (tid == 0) d_inv[row] = 1.f / red[0];
}

// ---------------- mma.sync GEMM: 128x128 tile, BK=32, 256 thr, 2 CTA/SM ------
// padded rows: 40 bf16 cols = 80 B. Each tile (128 rows) = 10240 B
#define ROWB     80
#define TILE_B   10240
#define STAGE_B  40960                 // Ah, Al, Bh, Bl
#define SM_BYTES (2 * STAGE_B)         // 81920 -> 2 CTAs/SM

template<int MODE>
__global__ __launch_bounds__(256, 2)
void k_tc(const float* __restrict__ fcb, float* __restrict__ outp)
{
    extern __shared__ char smem[];
    const uint32_t sb = smem_u32(smem);
    const int tid = threadIdx.x;
    const int wid = tid >> 5, lane = tid & 31;
    const int wm = wid & 1, wn = wid >> 1;       // 2 x 4 warp grid; warp tile 64m x 32n

    const int n0 = blockIdx.x * 128;
    const int m0 = blockIdx.y * 128;             // local row for MODE 2, global else
    const int b  = (MODE == 2) ? blockIdx.z : (m0 >> 10);

    float acc[4][4][4] = {};

    const int NIT = 32;                          // K = 1024, BK = 32

    auto issue = [&](int c) {
        const __nv_bfloat16 *Ah, *Al, *Bh, *Bl;
        int lda, ldb;
        if (MODE == 1) {
            lda = FIN; ldb = FIN;
            size_t ao = (size_t)m0 * FIN + c * 32;
            size_t bo = (size_t)n0 * FIN + c * 32;
            Ah = d_x_hi + ao;  Al = d_x_lo + ao;
            Bh = d_wt_hi + bo; Bl = d_wt_lo + bo;
        } else if (MODE == 2) {
            lda = NN; ldb = NN;
            size_t ao = (size_t)b * NN * NN + (size_t)m0 * NN + c * 32;
            size_t bo = (size_t)b * FOUT * NN + (size_t)n0 * NN + c * 32;
            Ah = d_att_hi + ao; Al = d_att_lo + ao;
            Bh = d_ht_hi + bo;  Bl = d_ht_lo + bo;
        } else {
            lda = FOUT; ldb = 2 * FOUT;
            size_t ao;
            if (c < 16) { ao = (size_t)m0 * FOUT + c * 32;        Ah = d_agg_hi + ao; Al = d_agg_lo + ao; }
            else        { ao = (size_t)m0 * FOUT + (c - 16) * 32; Ah = d_h_hi + ao;   Al = d_h_lo + ao; }
            size_t bo = (size_t)n0 * (2 * FOUT) + c * 32;
            Bh = d_fcw_hi + bo; Bl = d_fcw_lo + bo;
        }
        const uint32_t st = sb + (c & 1) * STAGE_B;
        #pragma unroll
        for (int i = 0; i < 2; i++) {
            int idx = tid + i * 256;
            int row = idx >> 2, seg = idx & 3;
            uint32_t so = row * ROWB + seg * 16;
            cp16(st + so,              Ah + (size_t)row * lda + seg * 8);
            cp16(st + TILE_B + so,     Al + (size_t)row * lda + seg * 8);
            cp16(st + 2 * TILE_B + so, Bh + (size_t)row * ldb + seg * 8);
            cp16(st + 3 * TILE_B + so, Bl + (size_t)row * ldb + seg * 8);
        }
        asm volatile("cp.async.commit_group;" ::: "memory");
    };

    issue(0);
    for (int c = 0; c < NIT; c++) {
        if (c + 1 < NIT) {
            issue(c + 1);
            asm volatile("cp.async.wait_group 1;" ::: "memory");
        } else {
            asm volatile("cp.async.wait_group 0;" ::: "memory");
        }
        __syncthreads();

        const uint32_t base = sb + (c & 1) * STAGE_B;
        #pragma unroll
        for (int ks = 0; ks < 2; ks++) {
            const int kb = ks * 32;               // 16 elements * 2B
            // load all B fragments first (16 regs live)
            uint32_t bh[4][2], bl[4][2];
            #pragma unroll
            for (int nt = 0; nt < 4; nt++) {
                uint32_t rb = base + 2 * TILE_B + (wn * 32 + nt * 8 + (lane & 7)) * ROWB
                            + kb + ((lane >> 3) & 1) * 16;
                ldsm2(bh[nt], rb);
                ldsm2(bl[nt], rb + TILE_B);
            }
            // stream A fragments per mt (8 regs live at a time)
            #pragma unroll
            for (int mt = 0; mt < 4; mt++) {
                uint32_t ah[4], al[4];
                uint32_t ra = base + (wm * 64 + mt * 16 + (lane & 15)) * ROWB + kb + (lane >> 4) * 16;
                ldsm4(ah, ra);
                ldsm4(al, ra + TILE_B);
                #pragma unroll
                for (int nt = 0; nt < 4; nt++) {
                    mma16816(acc[mt][nt], ah, bh[nt]);
                    mma16816(acc[mt][nt], ah, bl[nt]);
                    mma16816(acc[mt][nt], al, bh[nt]);
                }
            }
        }
        __syncthreads();
    }

    // ---------------- epilogue: direct fragment stores ----------------
    const int g = lane >> 2, tig = lane & 3;
    #pragma unroll
    for (int mt = 0; mt < 4; mt++) {
        const int lr0 = wm * 64 + mt * 16 + g;
        const int lr1 = lr0 + 8;
        float s0 = 1.f, s1 = 1.f;
        if (MODE == 2) {
            s0 = d_inv[b * NN + m0 + lr0];
            s1 = d_inv[b * NN + m0 + lr1];
        }
        #pragma unroll
        for (int nt = 0; nt < 4; nt++) {
            float* c = acc[mt][nt];
            const int ncol = n0 + wn * 32 + nt * 8 + tig * 2;
            if (MODE == 1) {
                unsigned h2, l2;
                split_pack(c[0], c[1], h2, l2);
                size_t o = (size_t)(m0 + lr0) * FOUT + ncol;
                *(unsigned*)(d_h_hi + o) = h2; *(unsigned*)(d_h_lo + o) = l2;
                split_pack(c[2], c[3], h2, l2);
                o = (size_t)(m0 + lr1) * FOUT + ncol;
                *(unsigned*)(d_h_hi + o) = h2; *(unsigned*)(d_h_lo + o) = l2;
            } else if (MODE == 2) {
                unsigned h2, l2;
                split_pack(c[0] * s0, c[1] * s0, h2, l2);
                size_t o = (size_t)(b * NN + m0 + lr0) * FOUT + ncol;
                *(unsigned*)(d_agg_hi + o) = h2; *(unsigned*)(d_agg_lo + o) = l2;
                split_pack(c[2] * s1, c[3] * s1, h2, l2);
                o = (size_t)(b * NN + m0 + lr1) * FOUT + ncol;
                *(unsigned*)(d_agg_hi + o) = h2; *(unsigned*)(d_agg_lo + o) = l2;
            } else {
                float b0 = fcb[ncol], b1 = fcb[ncol + 1];
                float v0 = c[0] + b0, v1 = c[1] + b1;
                v0 = v0 > 0.f ? v0 : expm1f(v0);
                v1 = v1 > 0.f ? v1 : expm1f(v1);
                *(float2*)(outp + (size_t)(m0 + lr0) * FOUT + ncol) = make_float2(v0, v1);
                float v2 = c[2] + b0, v3 = c[3] + b1;
                v2 = v2 > 0.f ? v2 : expm1f(v2);
                v3 = v3 > 0.f ? v3 : expm1f(v3);
                *(float2*)(outp + (size_t)(m0 + lr1) * FOUT + ncol) = make_float2(v2, v3);
            }
        }
    }
}

// ---------------- launch -----------------------------------------------------
extern "C" void kernel_launch(void* const* d_in, const int* in_sizes, int n_in,
                              void* d_out, int out_size)
{
    const float* x   = (const float*)d_in[0];
    const int*   adj = (const int*)  d_in[1];
    const float* W   = (const float*)d_in[2];
    const float* a   = (const float*)d_in[3];
    const float* fcw = (const float*)d_in[4];
    const float* fcb = (const float*)d_in[5];
    float* out = (float*)d_out;

    cudaFuncSetAttribute(k_tc<1>, cudaFuncAttributeMaxDynamicSharedMemorySize, SM_BYTES);
    cudaFuncSetAttribute(k_tc<2>, cudaFuncAttributeMaxDynamicSharedMemorySize, SM_BYTES);
    cudaFuncSetAttribute(k_tc<3>, cudaFuncAttributeMaxDynamicSharedMemorySize, SM_BYTES);

    __nv_bfloat16 *xh, *xl, *fh, *fl;
    cudaGetSymbolAddress((void**)&xh, d_x_hi);
    cudaGetSymbolAddress((void**)&xl, d_x_lo);
    cudaGetSymbolAddress((void**)&fh, d_fcw_hi);
    cudaGetSymbolAddress((void**)&fl, d_fcw_lo);

    // conversions
    k_cvt_pair<<<(MTOT * FIN / 2 + 255) / 256, 256>>>(x, xh, xl, MTOT * FIN / 2);
    k_cvt_wt  <<<(FOUT * FIN + 255) / 256, 256>>>(W);
    k_cvt_pair<<<(FOUT * 2 * FOUT / 2 + 255) / 256, 256>>>(fcw, fh, fl, FOUT * 2 * FOUT / 2);

    // 1) h = x @ W
    k_tc<1><<<dim3(FOUT / 128, MTOT / 128), 256, SM_BYTES>>>(nullptr, nullptr);
    // 1b) h^T per batch (hi & lo)
    k_tr<<<dim3(FOUT / 32, NN / 32, BB * 2), dim3(32, 8)>>>();
    // 2) f1, f2
    k_f12<<<(MTOT * 32) / 256, 256>>>(a);
    // 3) attention numerators + inverse row sums
    k_att<<<MTOT, 256>>>(adj);
    // 4) agg = softmax(att) @ h
    k_tc<2><<<dim3(FOUT / 128, NN / 128, BB), 256, SM_BYTES>>>(nullptr, nullptr);
    // 5) out = elu([agg, h] @ fc_w^T + fc_b)
    k_tc<3><<<dim3(FOUT / 128, MTOT / 128), 256, SM_BYTES>>>(fcb, out);
}

// round 6
// speedup vs baseline: 3.2557x; 1.0345x over previous
#include <cuda_runtime.h>
#include <cuda_bf16.h>
#include <math.h>
#include <stdint.h>

#define ALPHA_SLOPE 0.2f
#define NEG_INF_F   -9000000000000000.0f

#define BB    16
#define NN    1024
#define FIN   1024
#define FOUT  512
#define MTOT  (BB*NN)        // 16384

// ---------------- scratch (static device globals) ---------------------------
__device__ __nv_bfloat16 d_x_hi [(size_t)MTOT * FIN];
__device__ __nv_bfloat16 d_x_lo [(size_t)MTOT * FIN];
__device__ __nv_bfloat16 d_wt_hi[(size_t)FOUT * FIN];      // W^T [512][1024]
__device__ __nv_bfloat16 d_wt_lo[(size_t)FOUT * FIN];
__device__ __nv_bfloat16 d_fcw_hi[(size_t)FOUT * 2 * FOUT];
__device__ __nv_bfloat16 d_fcw_lo[(size_t)FOUT * 2 * FOUT];
__device__ __nv_bfloat16 d_h_hi [(size_t)MTOT * FOUT];
__device__ __nv_bfloat16 d_h_lo [(size_t)MTOT * FOUT];
__device__ __nv_bfloat16 d_ht_hi[(size_t)BB * FOUT * NN];  // h^T per batch [512][1024]
__device__ __nv_bfloat16 d_ht_lo[(size_t)BB * FOUT * NN];
__device__ __nv_bfloat16 d_att_hi[(size_t)MTOT * NN];
__device__ __nv_bfloat16 d_att_lo[(size_t)MTOT * NN];
__device__ __nv_bfloat16 d_agg_hi[(size_t)MTOT * FOUT];
__device__ __nv_bfloat16 d_agg_lo[(size_t)MTOT * FOUT];
__device__ float d_f1 [MTOT];
__device__ float d_f2 [MTOT];
__device__ float d_inv[MTOT];

// ---------------- helpers ----------------------------------------------------
__device__ __forceinline__ uint32_t smem_u32(const void* p) {
    uint32_t a;
    asm("{ .reg .u64 t; cvta.to.shared.u64 t, %1; cvt.u32.u64 %0, t; }" : "=r"(a) : "l"(p));
    return a;
}
__device__ __forceinline__ void cp16(uint32_t s, const void* g) {
    asm volatile("cp.async.cg.shared.global [%0], [%1], 16;" :: "r"(s), "l"(g));
}
__device__ __forceinline__ void ldsm4(uint32_t* r, uint32_t addr) {
    asm volatile("ldmatrix.sync.aligned.m8n8.x4.shared.b16 {%0,%1,%2,%3}, [%4];"
        : "=r"(r[0]), "=r"(r[1]), "=r"(r[2]), "=r"(r[3]) : "r"(addr));
}
__device__ __forceinline__ void mma16816(float* c, const uint32_t* a, const uint32_t* b) {
    asm volatile("mma.sync.aligned.m16n8k16.row.col.f32.bf16.bf16.f32 "
        "{%0,%1,%2,%3}, {%4,%5,%6,%7}, {%8,%9}, {%0,%1,%2,%3};"
        : "+f"(c[0]), "+f"(c[1]), "+f"(c[2]), "+f"(c[3])
        : "r"(a[0]), "r"(a[1]), "r"(a[2]), "r"(a[3]), "r"(b[0]), "r"(b[1]));
}

// ---------------- fp32 -> bf16 hi/lo split ----------------------------------
__device__ __forceinline__ void split1(float v, __nv_bfloat16& h, __nv_bfloat16& l) {
    h = __float2bfloat16(v);
    l = __float2bfloat16(v - __bfloat162float(h));
}
__device__ __forceinline__ void split_pack(float v0, float v1, unsigned& h2, unsigned& l2) {
    __nv_bfloat16 h0, h1, l0, l1;
    split1(v0, h0, l0); split1(v1, h1, l1);
    h2 = ((unsigned)__bfloat16_as_ushort(h1) << 16) | __bfloat16_as_ushort(h0);
    l2 = ((unsigned)__bfloat16_as_ushort(l1) << 16) | __bfloat16_as_ushort(l0);
}

// ---------------- conversion kernels -----------------------------------------
__global__ void k_cvt_pair(const float* __restrict__ src, __nv_bfloat16* __restrict__ hi,
                           __nv_bfloat16* __restrict__ lo, int n2)
{
    int i = blockIdx.x * blockDim.x + threadIdx.x;
    if (i >= n2) return;
    float2 v = ((const float2*)src)[i];
    unsigned h2, l2; split_pack(v.x, v.y, h2, l2);
    ((unsigned*)hi)[i] = h2; ((unsigned*)lo)[i] = l2;
}

__global__ void k_cvt_wt(const float* __restrict__ W)   // W[1024][512] -> Wt[512][1024]
{
    int i = blockIdx.x * blockDim.x + threadIdx.x;       // 524288
    int n = i >> 10, k = i & 1023;
    float v = W[(size_t)k * FOUT + n];
    split1(v, d_wt_hi[i], d_wt_lo[i]);
}

// ---------------- transpose h -> h^T (per batch) ------------------------------
__global__ void k_tr()
{
    __shared__ __nv_bfloat16 t[32][33];
    const int z = blockIdx.z;
    const int b = z >> 1;
    const __nv_bfloat16* src = (z & 1) ? d_h_lo : d_h_hi;
    __nv_bfloat16*       dst = (z & 1) ? d_ht_lo : d_ht_hi;
    const int f0 = blockIdx.x * 32, n0 = blockIdx.y * 32;
    const int tx = threadIdx.x, ty = threadIdx.y;   // (32,8)
    #pragma unroll
    for (int i = 0; i < 4; i++) {
        int n = n0 + ty + i * 8;
        t[ty + i * 8][tx] = src[(size_t)(b * NN + n) * FOUT + f0 + tx];
    }
    __syncthreads();
    #pragma unroll
    for (int i = 0; i < 4; i++) {
        int f = f0 + ty + i * 8;
        dst[(size_t)(b * FOUT + f) * NN + n0 + tx] = t[tx][ty + i * 8];
    }
}

// ---------------- f1/f2 ------------------------------------------------------
__global__ void k_f12(const float* __restrict__ a)
{
    int row  = (blockIdx.x * blockDim.x + threadIdx.x) >> 5;
    int lane = threadIdx.x & 31;
    if (row >= MTOT) return;
    const __nv_bfloat16* hh = d_h_hi + (size_t)row * FOUT;
    const __nv_bfloat16* hl = d_h_lo + (size_t)row * FOUT;
    float s1 = 0.f, s2 = 0.f;
    for (int k = lane; k < FOUT; k += 32) {
        float hv = __bfloat162float(hh[k]) + __bfloat162float(hl[k]);
        s1 = fmaf(hv, a[k], s1);
        s2 = fmaf(hv, a[FOUT + k], s2);
    }
    #pragma unroll
    for (int o = 16; o; o >>= 1) {
        s1 += __shfl_xor_sync(0xffffffffu, s1, o);
        s2 += __shfl_xor_sync(0xffffffffu, s2, o);
    }
    if (lane == 0) { d_f1[row] = s1; d_f2[row] = s2; }
}

// ---------------- attention numerators (bf16 hi/lo) + 1/rowsum ---------------
__global__ void k_att(const int* __restrict__ adj)
{
    const int row = blockIdx.x;
    const int b   = row >> 10;
    const int tid = threadIdx.x;

    __shared__ float sh[NN];
    __shared__ float red[256];

    const float f1i = d_f1[row];
    const int*   arow = adj + (size_t)row * NN;
    const float* f2b  = d_f2 + b * NN;

    float lmax = -INFINITY;
    for (int j = tid; j < NN; j += 256) {
        float e = f1i + f2b[j];
        e = e > 0.f ? e : ALPHA_SLOPE * e;
        e = (arow[j] > 0) ? e : NEG_INF_F;
        sh[j] = e;
        lmax = fmaxf(lmax, e);
    }
    red[tid] = lmax;
    __syncthreads();
    for (int s = 128; s; s >>= 1) {
        if (tid < s) red[tid] = fmaxf(red[tid], red[tid + s]);
        __syncthreads();
    }
    const float m = red[0];
    __syncthreads();

    float lsum = 0.f;
    __nv_bfloat16* ph = d_att_hi + (size_t)row * NN;
    __nv_bfloat16* pl = d_att_lo + (size_t)row * NN;
    for (int j = tid; j < NN; j += 256) {
        float p = __expf(sh[j] - m);
        __nv_bfloat16 hh, ll; split1(p, hh, ll);
        ph[j] = hh; pl[j] = ll;
        lsum += p;
    }
    red[tid] = lsum;
    __syncthreads();
    for (int s = 128; s; s >>= 1) {
        if (tid < s) red[tid] += red[tid + s];
        __syncthreads();
    }
    if (tid == 0) d_inv[row] = 1.f / red[0];
}

// ---------------- mma.sync GEMM: 128x128 tile, BK=32, 256 thr, 2 CTA/SM ------
// padded rows: 40 bf16 cols = 80 B. Each tile (128 rows) = 10240 B
#define ROWB     80
#define TILE_B   10240
#define STAGE_B  40960                 // Ah, Al, Bh, Bl
#define SM_BYTES (2 * STAGE_B)         // 81920 -> 2 CTAs/SM

template<int MODE>
__global__ __launch_bounds__(256, 2)
void k_tc(const float* __restrict__ fcb, float* __restrict__ outp)
{
    extern __shared__ char smem[];
    const uint32_t sb = smem_u32(smem);
    const int tid = threadIdx.x;
    const int wid = tid >> 5, lane = tid & 31;
    const int wm = wid & 1, wn = wid >> 1;       // 2 x 4 warp grid; warp tile 64m x 32n

    const int n0 = blockIdx.x * 128;
    const int m0 = blockIdx.y * 128;             // local row for MODE 2, global else
    const int b  = (MODE == 2) ? blockIdx.z : (m0 >> 10);

    float acc[4][4][4] = {};

    const int NIT = 32;                          // K = 1024, BK = 32

    auto issue = [&](int c) {
        const __nv_bfloat16 *Ah, *Al, *Bh, *Bl;
        int lda, ldb;
        if (MODE == 1) {
            lda = FIN; ldb = FIN;
            size_t ao = (size_t)m0 * FIN + c * 32;
            size_t bo = (size_t)n0 * FIN + c * 32;
            Ah = d_x_hi + ao;  Al = d_x_lo + ao;
            Bh = d_wt_hi + bo; Bl = d_wt_lo + bo;
        } else if (MODE == 2) {
            lda = NN; ldb = NN;
            size_t ao = (size_t)b * NN * NN + (size_t)m0 * NN + c * 32;
            size_t bo = (size_t)b * FOUT * NN + (size_t)n0 * NN + c * 32;
            Ah = d_att_hi + ao; Al = d_att_lo + ao;
            Bh = d_ht_hi + bo;  Bl = d_ht_lo + bo;
        } else {
            lda = FOUT; ldb = 2 * FOUT;
            size_t ao;
            if (c < 16) { ao = (size_t)m0 * FOUT + c * 32;        Ah = d_agg_hi + ao; Al = d_agg_lo + ao; }
            else        { ao = (size_t)m0 * FOUT + (c - 16) * 32; Ah = d_h_hi + ao;   Al = d_h_lo + ao; }
            size_t bo = (size_t)n0 * (2 * FOUT) + c * 32;
            Bh = d_fcw_hi + bo; Bl = d_fcw_lo + bo;
        }
        const uint32_t st = sb + (c & 1) * STAGE_B;
        #pragma unroll
        for (int i = 0; i < 2; i++) {
            int idx = tid + i * 256;
            int row = idx >> 2, seg = idx & 3;
            uint32_t so = row * ROWB + seg * 16;
            cp16(st + so,              Ah + (size_t)row * lda + seg * 8);
            cp16(st + TILE_B + so,     Al + (size_t)row * lda + seg * 8);
            cp16(st + 2 * TILE_B + so, Bh + (size_t)row * ldb + seg * 8);
            cp16(st + 3 * TILE_B + so, Bl + (size_t)row * ldb + seg * 8);
        }
        asm volatile("cp.async.commit_group;" ::: "memory");
    };

    issue(0);
    #pragma unroll 1
    for (int c = 0; c < NIT; c++) {
        asm volatile("cp.async.wait_group 0;" ::: "memory");
        __syncthreads();                 // data of stage c visible; all warps done
                                         // reading stage (c+1)&1 (last read iter c-1)
        if (c + 1 < NIT) issue(c + 1);   // fills the other buffer async during compute

        const uint32_t base = sb + (c & 1) * STAGE_B;
        #pragma unroll
        for (int ks = 0; ks < 2; ks++) {
            const int kb = ks * 32;               // 16 elements * 2B
            // B fragments: one ldsm4 covers two nt tiles (lanes 16-31 -> nt+1)
            uint32_t bh[4][2], bl[4][2];
            #pragma unroll
            for (int nt2 = 0; nt2 < 2; nt2++) {
                int ntt = nt2 * 2 + ((lane >> 4) & 1);
                uint32_t rb = base + 2 * TILE_B + (wn * 32 + ntt * 8 + (lane & 7)) * ROWB
                            + kb + ((lane >> 3) & 1) * 16;
                uint32_t r[4];
                ldsm4(r, rb);
                bh[nt2*2][0] = r[0]; bh[nt2*2][1] = r[1];
                bh[nt2*2+1][0] = r[2]; bh[nt2*2+1][1] = r[3];
                ldsm4(r, rb + TILE_B);
                bl[nt2*2][0] = r[0]; bl[nt2*2][1] = r[1];
                bl[nt2*2+1][0] = r[2]; bl[nt2*2+1][1] = r[3];
            }
            // A streamed per mt; product-major order inside mt (same-acc distance 4)
            #pragma unroll
            for (int mt = 0; mt < 4; mt++) {
                uint32_t ah[4], al[4];
                uint32_t ra = base + (wm * 64 + mt * 16 + (lane & 15)) * ROWB + kb + (lane >> 4) * 16;
                ldsm4(ah, ra);
                ldsm4(al, ra + TILE_B);
                #pragma unroll
                for (int nt = 0; nt < 4; nt++) mma16816(acc[mt][nt], ah, bh[nt]);
                #pragma unroll
                for (int nt = 0; nt < 4; nt++) mma16816(acc[mt][nt], ah, bl[nt]);
                #pragma unroll
                for (int nt = 0; nt < 4; nt++) mma16816(acc[mt][nt], al, bh[nt]);
            }
        }
        // no trailing sync: next iteration's top sync provides the RAW/WAR barrier
    }

    __syncthreads();

    // ---------------- epilogue: direct fragment stores ----------------
    const int g = lane >> 2, tig = lane & 3;
    #pragma unroll
    for (int mt = 0; mt < 4; mt++) {
        const int lr0 = wm * 64 + mt * 16 + g;
        const int lr1 = lr0 + 8;
        float s0 = 1.f, s1 = 1.f;
        if (MODE == 2) {
            s0 = d_inv[b * NN + m0 + lr0];
            s1 = d_inv[b * NN + m0 + lr1];
        }
        #pragma unroll
        for (int nt = 0; nt < 4; nt++) {
            float* c = acc[mt][nt];
            const int ncol = n0 + wn * 32 + nt * 8 + tig * 2;
            if (MODE == 1) {
                unsigned h2, l2;
                split_pack(c[0], c[1], h2, l2);
                size_t o = (size_t)(m0 + lr0) * FOUT + ncol;
                *(unsigned*)(d_h_hi + o) = h2; *(unsigned*)(d_h_lo + o) = l2;
                split_pack(c[2], c[3], h2, l2);
                o = (size_t)(m0 + lr1) * FOUT + ncol;
                *(unsigned*)(d_h_hi + o) = h2; *(unsigned*)(d_h_lo + o) = l2;
            } else if (MODE == 2) {
                unsigned h2, l2;
                split_pack(c[0] * s0, c[1] * s0, h2, l2);
                size_t o = (size_t)(b * NN + m0 + lr0) * FOUT + ncol;
                *(unsigned*)(d_agg_hi + o) = h2; *(unsigned*)(d_agg_lo + o) = l2;
                split_pack(c[2] * s1, c[3] * s1, h2, l2);
                o = (size_t)(b * NN + m0 + lr1) * FOUT + ncol;
                *(unsigned*)(d_agg_hi + o) = h2; *(unsigned*)(d_agg_lo + o) = l2;
            } else {
                float b0 = fcb[ncol], b1 = fcb[ncol + 1];
                float v0 = c[0] + b0, v1 = c[1] + b1;
                v0 = v0 > 0.f ? v0 : expm1f(v0);
                v1 = v1 > 0.f ? v1 : expm1f(v1);
                *(float2*)(outp + (size_t)(m0 + lr0) * FOUT + ncol) = make_float2(v0, v1);
                float v2 = c[2] + b0, v3 = c[3] + b1;
                v2 = v2 > 0.f ? v2 : expm1f(v2);
                v3 = v3 > 0.f ? v3 : expm1f(v3);
                *(float2*)(outp + (size_t)(m0 + lr1) * FOUT + ncol) = make_float2(v2, v3);
            }
        }
    }
}

// ---------------- launch -----------------------------------------------------
extern "C" void kernel_launch(void* const* d_in, const int* in_sizes, int n_in,
                              void* d_out, int out_size)
{
    const float* x   = (const float*)d_in[0];
    const int*   adj = (const int*)  d_in[1];
    const float* W   = (const float*)d_in[2];
    const float* a   = (const float*)d_in[3];
    const float* fcw = (const float*)d_in[4];
    const float* fcb = (const float*)d_in[5];
    float* out = (float*)d_out;

    cudaFuncSetAttribute(k_tc<1>, cudaFuncAttributeMaxDynamicSharedMemorySize, SM_BYTES);
    cudaFuncSetAttribute(k_tc<2>, cudaFuncAttributeMaxDynamicSharedMemorySize, SM_BYTES);
    cudaFuncSetAttribute(k_tc<3>, cudaFuncAttributeMaxDynamicSharedMemorySize, SM_BYTES);

    __nv_bfloat16 *xh, *xl, *fh, *fl;
    cudaGetSymbolAddress((void**)&xh, d_x_hi);
    cudaGetSymbolAddress((void**)&xl, d_x_lo);
    cudaGetSymbolAddress((void**)&fh, d_fcw_hi);
    cudaGetSymbolAddress((void**)&fl, d_fcw_lo);

    // conversions
    k_cvt_pair<<<(MTOT * FIN / 2 + 255) / 256, 256>>>(x, xh, xl, MTOT * FIN / 2);
    k_cvt_wt  <<<(FOUT * FIN + 255) / 256, 256>>>(W);
    k_cvt_pair<<<(FOUT * 2 * FOUT / 2 + 255) / 256, 256>>>(fcw, fh, fl, FOUT * 2 * FOUT / 2);

    // 1) h = x @ W
    k_tc<1><<<dim3(FOUT / 128, MTOT / 128), 256, SM_BYTES>>>(nullptr, nullptr);
    // 1b) h^T per batch (hi & lo)
    k_tr<<<dim3(FOUT / 32, NN / 32, BB * 2), dim3(32, 8)>>>();
    // 2) f1, f2
    k_f12<<<(MTOT * 32) / 256, 256>>>(a);
    // 3) attention numerators + inverse row sums
    k_att<<<MTOT, 256>>>(adj);
    // 4) agg = softmax(att) @ h
    k_tc<2><<<dim3(FOUT / 128, NN / 128, BB), 256, SM_BYTES>>>(nullptr, nullptr);
    // 5) out = elu([agg, h] @ fc_w^T + fc_b)
    k_tc<3><<<dim3(FOUT / 128, MTOT / 128), 256, SM_BYTES>>>(fcb, out);
}

// round 7
// speedup vs baseline: 3.5720x; 1.0971x over previous
#include <cuda_runtime.h>
#include <cuda_bf16.h>
#include <math.h>
#include <stdint.h>

#define ALPHA_SLOPE 0.2f
#define NEG_INF_F   -9000000000000000.0f

#define BB    16
#define NN    1024
#define FIN   1024
#define FOUT  512
#define MTOT  (BB*NN)        // 16384

// ---------------- scratch (static device globals) ---------------------------
__device__ __nv_bfloat16 d_x_hi [(size_t)MTOT * FIN];
__device__ __nv_bfloat16 d_x_lo [(size_t)MTOT * FIN];
__device__ __nv_bfloat16 d_wt_hi[(size_t)FOUT * FIN];      // W^T [512][1024]
__device__ __nv_bfloat16 d_wt_lo[(size_t)FOUT * FIN];
__device__ __nv_bfloat16 d_fcw_hi[(size_t)FOUT * 2 * FOUT];
__device__ __nv_bfloat16 d_fcw_lo[(size_t)FOUT * 2 * FOUT];
__device__ __nv_bfloat16 d_h_hi [(size_t)MTOT * FOUT];
__device__ __nv_bfloat16 d_h_lo [(size_t)MTOT * FOUT];
__device__ __nv_bfloat16 d_ht_hi[(size_t)BB * FOUT * NN];  // h^T per batch [512][1024]
__device__ __nv_bfloat16 d_ht_lo[(size_t)BB * FOUT * NN];
__device__ __nv_bfloat16 d_att_hi[(size_t)MTOT * NN];
__device__ __nv_bfloat16 d_att_lo[(size_t)MTOT * NN];
__device__ __nv_bfloat16 d_agg_hi[(size_t)MTOT * FOUT];
__device__ __nv_bfloat16 d_agg_lo[(size_t)MTOT * FOUT];
__device__ float d_f1 [MTOT];
__device__ float d_f2 [MTOT];
__device__ float d_inv[MTOT];

// ---------------- helpers ----------------------------------------------------
__device__ __forceinline__ uint32_t smem_u32(const void* p) {
    uint32_t a;
    asm("{ .reg .u64 t; cvta.to.shared.u64 t, %1; cvt.u32.u64 %0, t; }" : "=r"(a) : "l"(p));
    return a;
}
__device__ __forceinline__ void cp16(uint32_t s, const void* g) {
    asm volatile("cp.async.cg.shared.global [%0], [%1], 16;" :: "r"(s), "l"(g));
}
__device__ __forceinline__ void ldsm4(uint32_t* r, uint32_t addr) {
    asm volatile("ldmatrix.sync.aligned.m8n8.x4.shared.b16 {%0,%1,%2,%3}, [%4];"
        : "=r"(r[0]), "=r"(r[1]), "=r"(r[2]), "=r"(r[3]) : "r"(addr));
}
__device__ __forceinline__ void mma16816(float* c, const uint32_t* a, const uint32_t* b) {
    asm volatile("mma.sync.aligned.m16n8k16.row.col.f32.bf16.bf16.f32 "
        "{%0,%1,%2,%3}, {%4,%5,%6,%7}, {%8,%9}, {%0,%1,%2,%3};"
        : "+f"(c[0]), "+f"(c[1]), "+f"(c[2]), "+f"(c[3])
        : "r"(a[0]), "r"(a[1]), "r"(a[2]), "r"(a[3]), "r"(b[0]), "r"(b[1]));
}

// ---------------- fp32 -> bf16 hi/lo split ----------------------------------
__device__ __forceinline__ void split1(float v, __nv_bfloat16& h, __nv_bfloat16& l) {
    h = __float2bfloat16(v);
    l = __float2bfloat16(v - __bfloat162float(h));
}
__device__ __forceinline__ void split_pack(float v0, float v1, unsigned& h2, unsigned& l2) {
    __nv_bfloat16 h0, h1, l0, l1;
    split1(v0, h0, l0); split1(v1, h1, l1);
    h2 = ((unsigned)__bfloat16_as_ushort(h1) << 16) | __bfloat16_as_ushort(h0);
    l2 = ((unsigned)__bfloat16_as_ushort(l1) << 16) | __bfloat16_as_ushort(l0);
}

// ---------------- conversion kernels -----------------------------------------
__global__ void k_cvt_pair(const float* __restrict__ src, __nv_bfloat16* __restrict__ hi,
                           __nv_bfloat16* __restrict__ lo, int n2)
{
    int i = blockIdx.x * blockDim.x + threadIdx.x;
    if (i >= n2) return;
    float2 v = ((const float2*)src)[i];
    unsigned h2, l2; split_pack(v.x, v.y, h2, l2);
    ((unsigned*)hi)[i] = h2; ((unsigned*)lo)[i] = l2;
}

__global__ void k_cvt_wt(const float* __restrict__ W)   // W[1024][512] -> Wt[512][1024]
{
    int i = blockIdx.x * blockDim.x + threadIdx.x;       // 524288
    int n = i >> 10, k = i & 1023;
    float v = W[(size_t)k * FOUT + n];
    split1(v, d_wt_hi[i], d_wt_lo[i]);
}

// ---------------- transpose h -> h^T (per batch) ------------------------------
__global__ void k_tr()
{
    __shared__ __nv_bfloat16 t[32][33];
    const int z = blockIdx.z;
    const int b = z >> 1;
    const __nv_bfloat16* src = (z & 1) ? d_h_lo : d_h_hi;
    __nv_bfloat16*       dst = (z & 1) ? d_ht_lo : d_ht_hi;
    const int f0 = blockIdx.x * 32, n0 = blockIdx.y * 32;
    const int tx = threadIdx.x, ty = threadIdx.y;   // (32,8)
    #pragma unroll
    for (int i = 0; i < 4; i++) {
        int n = n0 + ty + i * 8;
        t[ty + i * 8][tx] = src[(size_t)(b * NN + n) * FOUT + f0 + tx];
    }
    __syncthreads();
    #pragma unroll
    for (int i = 0; i < 4; i++) {
        int f = f0 + ty + i * 8;
        dst[(size_t)(b * FOUT + f) * NN + n0 + tx] = t[tx][ty + i * 8];
    }
}

// ---------------- f1/f2 ------------------------------------------------------
__global__ void k_f12(const float* __restrict__ a)
{
    int row  = (blockIdx.x * blockDim.x + threadIdx.x) >> 5;
    int lane = threadIdx.x & 31;
    if (row >= MTOT) return;
    const __nv_bfloat16* hh = d_h_hi + (size_t)row * FOUT;
    const __nv_bfloat16* hl = d_h_lo + (size_t)row * FOUT;
    float s1 = 0.f, s2 = 0.f;
    for (int k = lane; k < FOUT; k += 32) {
        float hv = __bfloat162float(hh[k]) + __bfloat162float(hl[k]);
        s1 = fmaf(hv, a[k], s1);
        s2 = fmaf(hv, a[FOUT + k], s2);
    }
    #pragma unroll
    for (int o = 16; o; o >>= 1) {
        s1 += __shfl_xor_sync(0xffffffffu, s1, o);
        s2 += __shfl_xor_sync(0xffffffffu, s2, o);
    }
    if (lane == 0) { d_f1[row] = s1; d_f2[row] = s2; }
}

// ---------------- attention numerators (bf16 hi/lo) + 1/rowsum ---------------
__global__ void k_att(const int* __restrict__ adj)
{
    const int row = blockIdx.x;
    const int b   = row >> 10;
    const int tid = threadIdx.x;

    __shared__ float sh[NN];
    __shared__ float red[256];

    const float f1i = d_f1[row];
    const int*   arow = adj + (size_t)row * NN;
    const float* f2b  = d_f2 + b * NN;

    float lmax = -INFINITY;
    for (int j = tid; j < NN; j += 256) {
        float e = f1i + f2b[j];
        e = e > 0.f ? e : ALPHA_SLOPE * e;
        e = (arow[j] > 0) ? e : NEG_INF_F;
        sh[j] = e;
        lmax = fmaxf(lmax, e);
    }
    red[tid] = lmax;
    __syncthreads();
    for (int s = 128; s; s >>= 1) {
        if (tid < s) red[tid] = fmaxf(red[tid], red[tid + s]);
        __syncthreads();
    }
    const float m = red[0];
    __syncthreads();

    float lsum = 0.f;
    __nv_bfloat16* ph = d_att_hi + (size_t)row * NN;
    __nv_bfloat16* pl = d_att_lo + (size_t)row * NN;
    for (int j = tid; j < NN; j += 256) {
        float p = __expf(sh[j] - m);
        __nv_bfloat16 hh, ll; split1(p, hh, ll);
        ph[j] = hh; pl[j] = ll;
        lsum += p;
    }
    red[tid] = lsum;
    __syncthreads();
    for (int s = 128; s; s >>= 1) {
        if (tid < s) red[tid] += red[tid + s];
        __syncthreads();
    }
    if (tid == 0) d_inv[row] = 1.f / red[0];
}

// ---------------- mma.sync GEMM: 128x128 tile, BK=32, SW128 smem, 3 stages ---
// Each smem row = 128B: [hi 32 elems (64B) | lo 32 elems (64B)], SW128 swizzled:
// phys = row*128 + (col16B*16 ^ ((row&7)<<4)). A tile 16KB, B tile 16KB.
#define TILE_B   16384
#define STAGE_B  32768                 // A + B combined tiles
#define NSTAGE   3
#define SM_BYTES (NSTAGE * STAGE_B)    // 98304 -> 2 CTAs/SM

__device__ __forceinline__ uint32_t sw_off(int row, int colb) {
    return (uint32_t)(row * 128 + (colb ^ ((row & 7) << 4)));
}

template<int MODE>
__global__ __launch_bounds__(256, 2)
void k_tc(const float* __restrict__ fcb, float* __restrict__ outp)
{
    extern __shared__ char smem[];
    const uint32_t sb = smem_u32(smem);
    const int tid = threadIdx.x;
    const int wid = tid >> 5, lane = tid & 31;
    const int wm = wid & 1, wn = wid >> 1;       // 2 x 4 warp grid; warp tile 64m x 32n

    const int n0 = blockIdx.x * 128;
    const int m0 = blockIdx.y * 128;             // local row for MODE 2, global else
    const int b  = (MODE == 2) ? blockIdx.z : (m0 >> 10);

    float acc[4][4][4] = {};

    const int NIT = 32;                          // K = 1024, BK = 32

    auto issue = [&](int c) {
        const __nv_bfloat16 *Ah, *Al, *Bh, *Bl;
        int lda, ldb;
        if (MODE == 1) {
            lda = FIN; ldb = FIN;
            size_t ao = (size_t)m0 * FIN + c * 32;
            size_t bo = (size_t)n0 * FIN + c * 32;
            Ah = d_x_hi + ao;  Al = d_x_lo + ao;
            Bh = d_wt_hi + bo; Bl = d_wt_lo + bo;
        } else if (MODE == 2) {
            lda = NN; ldb = NN;
            size_t ao = (size_t)b * NN * NN + (size_t)m0 * NN + c * 32;
            size_t bo = (size_t)b * FOUT * NN + (size_t)n0 * NN + c * 32;
            Ah = d_att_hi + ao; Al = d_att_lo + ao;
            Bh = d_ht_hi + bo;  Bl = d_ht_lo + bo;
        } else {
            lda = FOUT; ldb = 2 * FOUT;
            size_t ao = (size_t)m0 * FOUT + (c & 15) * 32;
            if (c < 16) { Ah = d_agg_hi + ao; Al = d_agg_lo + ao; }
            else        { Ah = d_h_hi + ao;   Al = d_h_lo + ao; }
            size_t bo = (size_t)n0 * (2 * FOUT) + c * 32;
            Bh = d_fcw_hi + bo; Bl = d_fcw_lo + bo;
        }
        const uint32_t st = sb + (c % NSTAGE) * STAGE_B;
        // A: 128 rows x 8 chunks (4 hi + 4 lo) = 1024; 4 per thread
        #pragma unroll
        for (int i = 0; i < 4; i++) {
            int idx = tid + i * 256;
            int row = idx >> 3, s = idx & 7;
            const __nv_bfloat16* src = (s < 4 ? Ah : Al) + (size_t)row * lda + (s & 3) * 8;
            cp16(st + sw_off(row, s * 16), src);
        }
        // B: same shape
        #pragma unroll
        for (int i = 0; i < 4; i++) {
            int idx = tid + i * 256;
            int row = idx >> 3, s = idx & 7;
            const __nv_bfloat16* src = (s < 4 ? Bh : Bl) + (size_t)row * ldb + (s & 3) * 8;
            cp16(st + TILE_B + sw_off(row, s * 16), src);
        }
        asm volatile("cp.async.commit_group;" ::: "memory");
    };

    issue(0);
    issue(1);
    #pragma unroll 1
    for (int c = 0; c < NIT; c++) {
        if (c == NIT - 1) asm volatile("cp.async.wait_group 0;" ::: "memory");
        else              asm volatile("cp.async.wait_group 1;" ::: "memory");
        __syncthreads();                 // stage c readable; all warps done with the
                                         // buffer (c+2)%3 (last read at iter c-1)
        if (c + 2 < NIT) issue(c + 2);

        const uint32_t base = sb + (c % NSTAGE) * STAGE_B;
        #pragma unroll
        for (int ks = 0; ks < 2; ks++) {
            // B fragments: one ldsm4 covers two nt tiles (lanes>>4 -> ntt)
            uint32_t bh[4][2], bl[4][2];
            #pragma unroll
            for (int nt2 = 0; nt2 < 2; nt2++) {
                int ntt  = nt2 * 2 + ((lane >> 4) & 1);
                int row  = wn * 32 + ntt * 8 + (lane & 7);
                int colh = ks * 32 + ((lane >> 3) & 1) * 16;
                uint32_t r[4];
                ldsm4(r, base + TILE_B + sw_off(row, colh));
                bh[nt2*2][0] = r[0]; bh[nt2*2][1] = r[1];
                bh[nt2*2+1][0] = r[2]; bh[nt2*2+1][1] = r[3];
                ldsm4(r, base + TILE_B + sw_off(row, colh + 64));
                bl[nt2*2][0] = r[0]; bl[nt2*2][1] = r[1];
                bl[nt2*2+1][0] = r[2]; bl[nt2*2+1][1] = r[3];
            }
            // A streamed per mt; product-major order inside mt
            #pragma unroll
            for (int mt = 0; mt < 4; mt++) {
                int row  = wm * 64 + mt * 16 + (lane & 15);
                int colh = ks * 32 + (lane >> 4) * 16;
                uint32_t ah[4], al[4];
                ldsm4(ah, base + sw_off(row, colh));
                ldsm4(al, base + sw_off(row, colh + 64));
                #pragma unroll
                for (int nt = 0; nt < 4; nt++) mma16816(acc[mt][nt], ah, bh[nt]);
                #pragma unroll
                for (int nt = 0; nt < 4; nt++) mma16816(acc[mt][nt], ah, bl[nt]);
                #pragma unroll
                for (int nt = 0; nt < 4; nt++) mma16816(acc[mt][nt], al, bh[nt]);
            }
        }
        // next iteration's top sync provides the RAW/WAR barrier
    }

    __syncthreads();

    // ---------------- epilogue: direct fragment stores ----------------
    const int g = lane >> 2, tig = lane & 3;
    #pragma unroll
    for (int mt = 0; mt < 4; mt++) {
        const int lr0 = wm * 64 + mt * 16 + g;
        const int lr1 = lr0 + 8;
        float s0 = 1.f, s1 = 1.f;
        if (MODE == 2) {
            s0 = d_inv[b * NN + m0 + lr0];
            s1 = d_inv[b * NN + m0 + lr1];
        }
        #pragma unroll
        for (int nt = 0; nt < 4; nt++) {
            float* c = acc[mt][nt];
            const int ncol = n0 + wn * 32 + nt * 8 + tig * 2;
            if (MODE == 1) {
                unsigned h2, l2;
                split_pack(c[0], c[1], h2, l2);
                size_t o = (size_t)(m0 + lr0) * FOUT + ncol;
                *(unsigned*)(d_h_hi + o) = h2; *(unsigned*)(d_h_lo + o) = l2;
                split_pack(c[2], c[3], h2, l2);
                o = (size_t)(m0 + lr1) * FOUT + ncol;
                *(unsigned*)(d_h_hi + o) = h2; *(unsigned*)(d_h_lo + o) = l2;
            } else if (MODE == 2) {
                unsigned h2, l2;
                split_pack(c[0] * s0, c[1] * s0, h2, l2);
                size_t o = (size_t)(b * NN + m0 + lr0) * FOUT + ncol;
                *(unsigned*)(d_agg_hi + o) = h2; *(unsigned*)(d_agg_lo + o) = l2;
                split_pack(c[2] * s1, c[3] * s1, h2, l2);
                o = (size_t)(b * NN + m0 + lr1) * FOUT + ncol;
                *(unsigned*)(d_agg_hi + o) = h2; *(unsigned*)(d_agg_lo + o) = l2;
            } else {
                float b0 = fcb[ncol], b1 = fcb[ncol + 1];
                float v0 = c[0] + b0, v1 = c[1] + b1;
                v0 = v0 > 0.f ? v0 : expm1f(v0);
                v1 = v1 > 0.f ? v1 : expm1f(v1);
                *(float2*)(outp + (size_t)(m0 + lr0) * FOUT + ncol) = make_float2(v0, v1);
                float v2 = c[2] + b0, v3 = c[3] + b1;
                v2 = v2 > 0.f ? v2 : expm1f(v2);
                v3 = v3 > 0.f ? v3 : expm1f(v3);
                *(float2*)(outp + (size_t)(m0 + lr1) * FOUT + ncol) = make_float2(v2, v3);
            }
        }
    }
}

// ---------------- launch -----------------------------------------------------
extern "C" void kernel_launch(void* const* d_in, const int* in_sizes, int n_in,
                              void* d_out, int out_size)
{
    const float* x   = (const float*)d_in[0];
    const int*   adj = (const int*)  d_in[1];
    const float* W   = (const float*)d_in[2];
    const float* a   = (const float*)d_in[3];
    const float* fcw = (const float*)d_in[4];
    const float* fcb = (const float*)d_in[5];
    float* out = (float*)d_out;

    cudaFuncSetAttribute(k_tc<1>, cudaFuncAttributeMaxDynamicSharedMemorySize, SM_BYTES);
    cudaFuncSetAttribute(k_tc<2>, cudaFuncAttributeMaxDynamicSharedMemorySize, SM_BYTES);
    cudaFuncSetAttribute(k_tc<3>, cudaFuncAttributeMaxDynamicSharedMemorySize, SM_BYTES);

    __nv_bfloat16 *xh, *xl, *fh, *fl;
    cudaGetSymbolAddress((void**)&xh, d_x_hi);
    cudaGetSymbolAddress((void**)&xl, d_x_lo);
    cudaGetSymbolAddress((void**)&fh, d_fcw_hi);
    cudaGetSymbolAddress((void**)&fl, d_fcw_lo);

    // conversions
    k_cvt_pair<<<(MTOT * FIN / 2 + 255) / 256, 256>>>(x, xh, xl, MTOT * FIN / 2);
    k_cvt_wt  <<<(FOUT * FIN + 255) / 256, 256>>>(W);
    k_cvt_pair<<<(FOUT * 2 * FOUT / 2 + 255) / 256, 256>>>(fcw, fh, fl, FOUT * 2 * FOUT / 2);

    // 1) h = x @ W
    k_tc<1><<<dim3(FOUT / 128, MTOT / 128), 256, SM_BYTES>>>(nullptr, nullptr);
    // 1b) h^T per batch (hi & lo)
    k_tr<<<dim3(FOUT / 32, NN / 32, BB * 2), dim3(32, 8)>>>();
    // 2) f1, f2
    k_f12<<<(MTOT * 32) / 256, 256>>>(a);
    // 3) attention numerators + inverse row sums
    k_att<<<MTOT, 256>>>(adj);
    // 4) agg = softmax(att) @ h
    k_tc<2><<<dim3(FOUT / 128, NN / 128, BB), 256, SM_BYTES>>>(nullptr, nullptr);
    // 5) out = elu([agg, h] @ fc_w^T + fc_b)
    k_tc<3><<<dim3(FOUT / 128, MTOT / 128), 256, SM_BYTES>>>(fcb, out);
}